// round 9
// baseline (speedup 1.0000x reference)
#include <cuda_runtime.h>
#include <cuda_bf16.h>
#include <cstdint>

#define NMAX 50000
#define EMAX 600000
#define DIM 128
#define BN_EPS 1e-5f

// ---------------- device scratch (no allocations allowed) ----------------
__device__ int   g_cnt[NMAX];
__device__ int   g_start[NMAX + 1];
__device__ int   g_cursor[NMAX];
__device__ int   g_src[EMAX];
__device__ int   g_bsum[64];
__device__ int   g_boff[64];
__device__ float g_deg_inv[NMAX];
__device__ float g_dis[NMAX];
__device__ __align__(16) float g_h[NMAX * DIM];      // GEMM output (fp32)
__device__ __align__(16) float g_z[NMAX * DIM];      // dis * relu(bn(h)) for next gather
__device__ __align__(16) float g_stats[2][256];      // per-BN-layer col sum / sumsq

// B weight images: bf16 split, ldmatrix-image layout per 128x128 chunk.
// sel: 0=W_out 1=W_root 2=W_sg1 3=W_sg2
__device__ __align__(16) uint32_t g_bhi[4][8192];
__device__ __align__(16) uint32_t g_blo[4][8192];

// ---------------- helpers ----------------
__device__ __forceinline__ uint32_t smem_u32(const void* p) {
    uint32_t a;
    asm("{ .reg .u64 t; cvta.to.shared.u64 t, %1; cvt.u32.u64 %0, t; }" : "=r"(a) : "l"(p));
    return a;
}
__device__ __forceinline__ uint32_t bf16pair(float lo, float hi) {
    uint32_t r;
    asm("cvt.rn.bf16x2.f32 %0, %1, %2;" : "=r"(r) : "f"(hi), "f"(lo));
    return r;
}
__device__ __forceinline__ float lo_f(uint32_t p) { return __uint_as_float(p << 16); }
__device__ __forceinline__ float hi_f(uint32_t p) { return __uint_as_float(p & 0xFFFF0000u); }

__device__ __forceinline__ void ldmx4(uint32_t* r, uint32_t addr) {
    asm volatile("ldmatrix.sync.aligned.m8n8.x4.shared.b16 {%0,%1,%2,%3}, [%4];"
                 : "=r"(r[0]), "=r"(r[1]), "=r"(r[2]), "=r"(r[3]) : "r"(addr));
}
__device__ __forceinline__ void ldmx2(uint32_t* r, uint32_t addr) {
    asm volatile("ldmatrix.sync.aligned.m8n8.x2.shared.b16 {%0,%1}, [%2];"
                 : "=r"(r[0]), "=r"(r[1]) : "r"(addr));
}
__device__ __forceinline__ void mma16816(float* d, const uint32_t* a, const uint32_t* b) {
    asm volatile("mma.sync.aligned.m16n8k16.row.col.f32.bf16.bf16.f32 "
                 "{%0,%1,%2,%3}, {%4,%5,%6,%7}, {%8,%9}, {%0,%1,%2,%3};"
                 : "+f"(d[0]), "+f"(d[1]), "+f"(d[2]), "+f"(d[3])
                 : "r"(a[0]), "r"(a[1]), "r"(a[2]), "r"(a[3]), "r"(b[0]), "r"(b[1]));
}

// ---------------- degree histogram ----------------
__global__ void deg_kernel(const int* __restrict__ col, int E) {
    int e = blockIdx.x * blockDim.x + threadIdx.x;
    if (e < E) atomicAdd(&g_cnt[col[e]], 1);
}

// ---------------- prefix scan (3 kernels, coalesced) ----------------
__global__ void scan1_kernel(int N) {
    __shared__ int sh[256];
    int b = blockIdx.x, t = threadIdx.x;
    int base = b * 1024 + t * 4;
    int s = 0;
#pragma unroll
    for (int q = 0; q < 4; q++) { int idx = base + q; if (idx < N) s += g_cnt[idx]; }
    sh[t] = s; __syncthreads();
    for (int st = 128; st > 0; st >>= 1) {
        if (t < st) sh[t] += sh[t + st];
        __syncthreads();
    }
    if (t == 0) g_bsum[b] = sh[0];
}
__global__ void scan2_kernel(int nb) {
    __shared__ int sh[64];
    int t = threadIdx.x;
    int own = (t < nb) ? g_bsum[t] : 0;
    sh[t] = own; __syncthreads();
    for (int st = 1; st < 64; st <<= 1) {
        int add = (t >= st) ? sh[t - st] : 0;
        __syncthreads();
        sh[t] += add;
        __syncthreads();
    }
    if (t < nb) g_boff[t] = sh[t] - own;
}
// scan3 also writes node norms (deg_inv / dis)
__global__ void scan3_kernel(int N, int E) {
    __shared__ int sh[256];
    int b = blockIdx.x, t = threadIdx.x;
    int base = b * 1024 + t * 4;
    int v[4]; int s = 0;
#pragma unroll
    for (int q = 0; q < 4; q++) { int idx = base + q; v[q] = (idx < N) ? g_cnt[idx] : 0; s += v[q]; }
    sh[t] = s; __syncthreads();
    for (int st = 1; st < 256; st <<= 1) {
        int add = (t >= st) ? sh[t - st] : 0;
        __syncthreads();
        sh[t] += add;
        __syncthreads();
    }
    int run = sh[t] - s + g_boff[b];
#pragma unroll
    for (int q = 0; q < 4; q++) {
        int idx = base + q;
        if (idx < N) {
            g_start[idx] = run;
            g_cursor[idx] = run;
            run += v[q];
            float d = (float)v[q];
            g_deg_inv[idx] = 1.0f / fmaxf(d, 1.0f);
            g_dis[idx] = rsqrtf(d + 1.0f);
        }
    }
    if (b == 0 && t == 0) g_start[N] = E;
}
__global__ void fill_kernel(const int* __restrict__ edge, int E) {
    int e = blockIdx.x * blockDim.x + threadIdx.x;
    if (e < E) {
        int r = __ldg(edge + e);
        int c = __ldg(edge + E + e);
        int pos = atomicAdd(&g_cursor[c], 1);
        g_src[pos] = r;
    }
}

// ---------------- B prep: weights -> bf16 split images ----------------
__global__ void bprep_kernel(const float* __restrict__ W_out, const float* __restrict__ W_root,
                             const float* __restrict__ W_sg1, const float* __restrict__ W_sg2) {
    int t = blockIdx.x * blockDim.x + threadIdx.x;  // 4 * 8192
    if (t >= 4 * 8192) return;
    int sel = t >> 13;
    int rem = t & 8191;
    int n = rem >> 6;
    int k = (rem & 63) << 1;
    const float* W = (sel == 0) ? W_out : (sel == 1) ? W_root : (sel == 2) ? W_sg1 : W_sg2;
    float x = __ldg(W + n * 128 + k);
    float y = __ldg(W + n * 128 + k + 1);
    uint32_t p = bf16pair(x, y);
    uint32_t q = bf16pair(x - lo_f(p), y - hi_f(p));
    g_bhi[sel][rem] = p;
    g_blo[sel][rem] = q;
}

// ---------------- fused gather + mma: one 128x128 output tile per block ----------------
// smem rows padded to 17 x 16B (272B) -> conflict-free ldmatrix
#define SROW 272
#define OFF_AHI 0
#define OFF_ALO 34816
#define OFF_BHI 69632
#define OFF_BLO 104448
#define SMEM_BYTES 139264

__device__ __forceinline__ void write_split_smem(char* smem, int rl, int lane, float4 v) {
    uint32_t p0 = bf16pair(v.x, v.y);
    uint32_t p1 = bf16pair(v.z, v.w);
    uint32_t q0 = bf16pair(v.x - lo_f(p0), v.y - hi_f(p0));
    uint32_t q1 = bf16pair(v.z - lo_f(p1), v.w - hi_f(p1));
    *(uint2*)(smem + OFF_AHI + rl * SROW + lane * 8) = make_uint2(p0, p1);
    *(uint2*)(smem + OFF_ALO + rl * SROW + lane * 8) = make_uint2(q0, q1);
}

// MODE 0 (layer 0): chunk0 A = deg_inv[n]*sum(emb[x_idx[r]]), B=W_out;
//                   chunk1 A = emb[x_idx[n]], B=W_root.
// MODE 1 (SGConv):  single chunk A = dis[n]*(sum(src[r]) + src[n]), B=W_sg.
template <int MODE, bool STATS, bool BIAS>
__global__ __launch_bounds__(256, 1)
void fused_kernel(const float* __restrict__ src, const int* __restrict__ x_idx,
                  const float* __restrict__ bias, float* __restrict__ H,
                  float* __restrict__ stats, int N, int bsel) {
    extern __shared__ __align__(16) char smem[];
    __shared__ float sstats[256];

    const int tid = threadIdx.x;
    const int wid = tid >> 5;
    const int lane = tid & 31;
    const int tile = blockIdx.x;
    const int warpRow = wid & 3;        // mma: 4 row groups of 32
    const int warpCol = wid >> 2;       // mma: 2 col groups of 64

    sstats[tid] = 0.f;
    const uint32_t smemu = smem_u32(smem);

    float acc[2][8][4];
#pragma unroll
    for (int mt = 0; mt < 2; mt++)
#pragma unroll
        for (int nt = 0; nt < 8; nt++)
#pragma unroll
            for (int q = 0; q < 4; q++) acc[mt][nt][q] = 0.f;

    // ldmatrix base addresses
    uint32_t aAddr[2][2];
#pragma unroll
    for (int mt = 0; mt < 2; mt++) {
        uint32_t rb = (uint32_t)(warpRow * 32 + mt * 16 + (lane & 15)) * SROW + ((lane >> 4) << 4);
        aAddr[mt][0] = smemu + OFF_AHI + rb;
        aAddr[mt][1] = smemu + OFF_ALO + rb;
    }
    uint32_t bRow = (uint32_t)(warpCol * 64 + (lane & 7)) * SROW + (((lane >> 3) & 1) << 4);
    uint32_t bAddrHi = smemu + OFF_BHI + bRow;
    uint32_t bAddrLo = smemu + OFF_BLO + bRow;

    const int KCHUNKS = (MODE == 0) ? 2 : 1;

#pragma unroll
    for (int c = 0; c < KCHUNKS; c++) {
        if (c > 0) __syncthreads();   // previous mma done reading smem
        // ---- stage B chunk ----
        {
            const int4* gBh = (const int4*)(g_bhi[bsel + c]);
            const int4* gBl = (const int4*)(g_blo[bsel + c]);
#pragma unroll
            for (int it = 0; it < 8; it++) {
                int idx = tid + it * 256;   // 0..2047
                int r = idx >> 4, ch = idx & 15;
                ((int4*)(smem + OFF_BHI))[r * 17 + ch] = __ldg(gBh + idx);
                ((int4*)(smem + OFF_BLO))[r * 17 + ch] = __ldg(gBl + idx);
            }
        }
        // ---- produce A chunk directly into smem (one warp per node, 16 nodes/warp) ----
        if (c == 0) {
            for (int j = 0; j < 16; j++) {
                int rl = wid * 16 + j;
                int n = tile * 128 + rl;
                float4 out = make_float4(0.f, 0.f, 0.f, 0.f);
                if (n < N) {
                    int s = __ldg(&g_start[n]);
                    int e = __ldg(&g_start[n + 1]);
                    float4 a0 = make_float4(0.f, 0.f, 0.f, 0.f);
                    float4 a1 = a0, a2 = a0, a3 = a0;
                    int i = s;
                    for (; i + 4 <= e; i += 4) {
                        const float* p[4];
#pragma unroll
                        for (int u = 0; u < 4; u++) {
                            int r = __ldg(&g_src[i + u]);
                            p[u] = (MODE == 0) ? src + (size_t)__ldg(x_idx + r) * DIM
                                               : src + (size_t)r * DIM;
                        }
                        float4 v0 = __ldg((const float4*)p[0] + lane);
                        float4 v1 = __ldg((const float4*)p[1] + lane);
                        float4 v2 = __ldg((const float4*)p[2] + lane);
                        float4 v3 = __ldg((const float4*)p[3] + lane);
                        a0.x += v0.x; a0.y += v0.y; a0.z += v0.z; a0.w += v0.w;
                        a1.x += v1.x; a1.y += v1.y; a1.z += v1.z; a1.w += v1.w;
                        a2.x += v2.x; a2.y += v2.y; a2.z += v2.z; a2.w += v2.w;
                        a3.x += v3.x; a3.y += v3.y; a3.z += v3.z; a3.w += v3.w;
                    }
                    for (; i < e; i++) {
                        int r = __ldg(&g_src[i]);
                        const float* p = (MODE == 0) ? src + (size_t)__ldg(x_idx + r) * DIM
                                                     : src + (size_t)r * DIM;
                        float4 v = __ldg((const float4*)p + lane);
                        a0.x += v.x; a0.y += v.y; a0.z += v.z; a0.w += v.w;
                    }
                    float4 a;
                    a.x = (a0.x + a1.x) + (a2.x + a3.x);
                    a.y = (a0.y + a1.y) + (a2.y + a3.y);
                    a.z = (a0.z + a1.z) + (a2.z + a3.z);
                    a.w = (a0.w + a1.w) + (a2.w + a3.w);
                    if (MODE == 0) {
                        float sc = g_deg_inv[n];
                        out = make_float4(sc * a.x, sc * a.y, sc * a.z, sc * a.w);
                    } else {
                        float sc = g_dis[n];
                        float4 z = __ldg((const float4*)(src + (size_t)n * DIM) + lane);
                        out = make_float4(sc * (a.x + z.x), sc * (a.y + z.y),
                                          sc * (a.z + z.z), sc * (a.w + z.w));
                    }
                }
                write_split_smem(smem, rl, lane, out);
            }
        } else {
            // chunk1 (MODE 0 only): root rows emb[x_idx[n]]
            for (int j = 0; j < 16; j++) {
                int rl = wid * 16 + j;
                int n = tile * 128 + rl;
                float4 v = make_float4(0.f, 0.f, 0.f, 0.f);
                if (n < N)
                    v = __ldg((const float4*)(src + (size_t)__ldg(x_idx + n) * DIM) + lane);
                write_split_smem(smem, rl, lane, v);
            }
        }
        __syncthreads();

        // ---- mma over 8 ksteps ----
#pragma unroll
        for (int ks = 0; ks < 8; ks++) {
            uint32_t ahi[2][4], alo[2][4];
#pragma unroll
            for (int mt = 0; mt < 2; mt++) {
                ldmx4(ahi[mt], aAddr[mt][0] + ks * 32);
                ldmx4(alo[mt], aAddr[mt][1] + ks * 32);
            }
#pragma unroll
            for (int nt = 0; nt < 8; nt++) {
                uint32_t bhi[2], blo[2];
                ldmx2(bhi, bAddrHi + nt * (8 * SROW) + ks * 32);
                ldmx2(blo, bAddrLo + nt * (8 * SROW) + ks * 32);
#pragma unroll
                for (int mt = 0; mt < 2; mt++) {
                    mma16816(acc[mt][nt], ahi[mt], bhi);
                    mma16816(acc[mt][nt], ahi[mt], blo);
                    mma16816(acc[mt][nt], alo[mt], bhi);
                }
            }
        }
    }

    // ---- epilogue: bias + store + BN stats ----
    const int rowbase = tile * 128 + warpRow * 32;
    const int colbase = warpCol * 64;

    float s[8][2], q[8][2];
#pragma unroll
    for (int nt = 0; nt < 8; nt++) { s[nt][0] = s[nt][1] = 0.f; q[nt][0] = q[nt][1] = 0.f; }

#pragma unroll
    for (int mt = 0; mt < 2; mt++) {
        int r0 = rowbase + mt * 16 + (lane >> 2);
        int r1 = r0 + 8;
#pragma unroll
        for (int nt = 0; nt < 8; nt++) {
            int col = colbase + nt * 8 + ((lane & 3) << 1);
            float b0 = BIAS ? __ldg(bias + col) : 0.f;
            float b1 = BIAS ? __ldg(bias + col + 1) : 0.f;
            float v0 = acc[mt][nt][0] + b0;
            float v1 = acc[mt][nt][1] + b1;
            float v2 = acc[mt][nt][2] + b0;
            float v3 = acc[mt][nt][3] + b1;
            if (r0 < N) {
                *(float2*)(H + (size_t)r0 * DIM + col) = make_float2(v0, v1);
                if (STATS) {
                    s[nt][0] += v0; s[nt][1] += v1;
                    q[nt][0] += v0 * v0; q[nt][1] += v1 * v1;
                }
            }
            if (r1 < N) {
                *(float2*)(H + (size_t)r1 * DIM + col) = make_float2(v2, v3);
                if (STATS) {
                    s[nt][0] += v2; s[nt][1] += v3;
                    q[nt][0] += v2 * v2; q[nt][1] += v3 * v3;
                }
            }
        }
    }

    if (STATS) {
#pragma unroll
        for (int nt = 0; nt < 8; nt++) {
#pragma unroll
            for (int p = 0; p < 2; p++) {
                float vs = s[nt][p], vq = q[nt][p];
#pragma unroll
                for (int sh = 4; sh < 32; sh <<= 1) {
                    vs += __shfl_xor_sync(0xFFFFFFFFu, vs, sh);
                    vq += __shfl_xor_sync(0xFFFFFFFFu, vq, sh);
                }
                if (lane < 4) {
                    int col = colbase + nt * 8 + (lane << 1) + p;
                    atomicAdd(&sstats[col], vs);
                    atomicAdd(&sstats[128 + col], vq);
                }
            }
        }
        __syncthreads();
        atomicAdd(&stats[tid], sstats[tid]);
    }
}

// ---------------- BN apply + ReLU + dis-prescale (z = dis * relu(bn(h))) ----------------
__global__ void bn_apply_kernel(const float* __restrict__ gamma, const float* __restrict__ beta,
                                const float* __restrict__ stats, int N) {
    __shared__ float4 ssc[32], ssh[32];
    int tid = threadIdx.x;
    if (tid < 32) {
        float4 s = ((const float4*)stats)[tid];
        float4 sq = ((const float4*)stats)[32 + tid];
        float4 g = __ldg((const float4*)gamma + tid);
        float4 b = __ldg((const float4*)beta + tid);
        float invn = 1.0f / (float)N;
        float4 mu = make_float4(s.x * invn, s.y * invn, s.z * invn, s.w * invn);
        float4 sc, sh;
        sc.x = g.x * rsqrtf(fmaxf(sq.x * invn - mu.x * mu.x, 0.f) + BN_EPS);
        sc.y = g.y * rsqrtf(fmaxf(sq.y * invn - mu.y * mu.y, 0.f) + BN_EPS);
        sc.z = g.z * rsqrtf(fmaxf(sq.z * invn - mu.z * mu.z, 0.f) + BN_EPS);
        sc.w = g.w * rsqrtf(fmaxf(sq.w * invn - mu.w * mu.w, 0.f) + BN_EPS);
        sh.x = b.x - mu.x * sc.x;
        sh.y = b.y - mu.y * sc.y;
        sh.z = b.z - mu.z * sc.z;
        sh.w = b.w - mu.w * sc.w;
        ssc[tid] = sc; ssh[tid] = sh;
    }
    __syncthreads();
    int i = blockIdx.x * blockDim.x + tid;
    int tot = N * (DIM / 4);
    if (i >= tot) return;
    int n = i >> 5;
    int q = i & 31;
    float4 h = reinterpret_cast<const float4*>(g_h)[i];
    float4 sc = ssc[q];
    float4 sh = ssh[q];
    float d = g_dis[n];
    float4 z;
    z.x = d * fmaxf(fmaf(h.x, sc.x, sh.x), 0.f);
    z.y = d * fmaxf(fmaf(h.y, sc.y, sh.y), 0.f);
    z.z = d * fmaxf(fmaf(h.z, sc.z, sh.z), 0.f);
    z.w = d * fmaxf(fmaf(h.w, sc.w, sh.w), 0.f);
    reinterpret_cast<float4*>(g_z)[i] = z;
}

// ---------------- launch ----------------
extern "C" void kernel_launch(void* const* d_in, const int* in_sizes, int n_in,
                              void* d_out, int out_size) {
    const int*   x_idx  = (const int*)d_in[0];
    const int*   edge   = (const int*)d_in[1];
    const float* emb    = (const float*)d_in[2];
    const float* W_out  = (const float*)d_in[3];
    const float* W_root = (const float*)d_in[4];
    const float* bn0_g  = (const float*)d_in[5];
    const float* bn0_b  = (const float*)d_in[6];
    const float* W_sg1  = (const float*)d_in[7];
    const float* b_sg1  = (const float*)d_in[8];
    const float* bn1_g  = (const float*)d_in[9];
    const float* bn1_b  = (const float*)d_in[10];
    const float* W_sg2  = (const float*)d_in[11];
    const float* b_sg2  = (const float*)d_in[12];
    float* out = (float*)d_out;

    int N = in_sizes[0];
    int E = in_sizes[1] / 2;

    void* hp = nullptr;   cudaGetSymbolAddress(&hp, g_h);
    void* zp = nullptr;   cudaGetSymbolAddress(&zp, g_z);
    void* cp = nullptr;   cudaGetSymbolAddress(&cp, g_cnt);
    void* sp = nullptr;   cudaGetSymbolAddress(&sp, g_stats);
    float* Hbuf = (float*)hp;
    float* Zbuf = (float*)zp;
    float* stats0 = (float*)sp;
    float* stats1 = stats0 + 256;

    cudaFuncSetAttribute(fused_kernel<0, true, false>, cudaFuncAttributeMaxDynamicSharedMemorySize, SMEM_BYTES);
    cudaFuncSetAttribute(fused_kernel<1, true, true>,  cudaFuncAttributeMaxDynamicSharedMemorySize, SMEM_BYTES);
    cudaFuncSetAttribute(fused_kernel<1, false, true>, cudaFuncAttributeMaxDynamicSharedMemorySize, SMEM_BYTES);

    const int nbElem = (N * (DIM / 4) + 255) / 256;
    const int nbEdgeT = (E + 255) / 256;
    const int nbScan = (N + 1023) / 1024;
    const int NT = (N + 127) / 128;

    // CSR build + norms + weight images
    cudaMemsetAsync(cp, 0, (size_t)N * sizeof(int));
    cudaMemsetAsync(sp, 0, 2 * 256 * sizeof(float));
    deg_kernel<<<nbEdgeT, 256>>>(edge + E, E);
    scan1_kernel<<<nbScan, 256>>>(N);
    scan2_kernel<<<1, 64>>>(nbScan);
    scan3_kernel<<<nbScan, 256>>>(N, E);
    fill_kernel<<<nbEdgeT, 256>>>(edge, E);
    bprep_kernel<<<128, 256>>>(W_out, W_root, W_sg1, W_sg2);

    // layer 0: ClusterGCN (gather+mma fused) -> BN -> ReLU
    fused_kernel<0, true, false><<<NT, 256, SMEM_BYTES>>>(emb, x_idx, nullptr, Hbuf, stats0, N, 0);
    bn_apply_kernel<<<nbElem, 256>>>(bn0_g, bn0_b, stats0, N);

    // layer 1: SGConv (fused) -> BN -> ReLU
    fused_kernel<1, true, true><<<NT, 256, SMEM_BYTES>>>(Zbuf, nullptr, b_sg1, Hbuf, stats1, N, 2);
    bn_apply_kernel<<<nbElem, 256>>>(bn1_g, bn1_b, stats1, N);

    // layer 2: final SGConv (fused) -> d_out
    fused_kernel<1, false, true><<<NT, 256, SMEM_BYTES>>>(Zbuf, nullptr, b_sg2, out, nullptr, N, 3);
}

// round 10
// speedup vs baseline: 1.7025x; 1.7025x over previous
#include <cuda_runtime.h>
#include <cuda_bf16.h>
#include <cstdint>

#define NMAX 50000
#define NPAD 50048          // 391 tiles * 128 rows
#define EMAX 600000
#define DIM 128
#define BN_EPS 1e-5f

// ---------------- device scratch (no allocations allowed) ----------------
__device__ int   g_cnt[NMAX];
__device__ int   g_start[NMAX + 1];
__device__ int   g_cursor[NMAX];
__device__ int   g_src[EMAX];
__device__ int   g_bsum[64];
__device__ int   g_boff[64];
__device__ float g_deg_inv[NMAX];
__device__ float g_dis[NMAX];
__device__ __align__(16) float g_h[NMAX * DIM];      // GEMM output (fp32)
__device__ float g_stats[2 * DIM];
__device__ __align__(16) float g_bnp[2 * DIM];       // BN scale / shift

// bf16 split images, row-major. A: [NPAD][256 bf16] (=128 u32). Layers 1/2 use cols 0..127.
__device__ __align__(16) uint32_t g_ahi[(size_t)NPAD * 128];
__device__ __align__(16) uint32_t g_alo[(size_t)NPAD * 128];
// B: [sel][128 n][128 k] bf16 = 8192 u32. sel: 0=W_out 1=W_root 2=W_sg1 3=W_sg2
__device__ __align__(16) uint32_t g_bhi[4][8192];
__device__ __align__(16) uint32_t g_blo[4][8192];

// ---------------- helpers ----------------
__device__ __forceinline__ uint32_t smem_u32(const void* p) {
    uint32_t a;
    asm("{ .reg .u64 t; cvta.to.shared.u64 t, %1; cvt.u32.u64 %0, t; }" : "=r"(a) : "l"(p));
    return a;
}
// pack two floats to bf16x2 (low half = first arg)
__device__ __forceinline__ uint32_t bf16pair(float lo, float hi) {
    uint32_t r;
    asm("cvt.rn.bf16x2.f32 %0, %1, %2;" : "=r"(r) : "f"(hi), "f"(lo));
    return r;
}
__device__ __forceinline__ float lo_f(uint32_t p) { return __uint_as_float(p << 16); }
__device__ __forceinline__ float hi_f(uint32_t p) { return __uint_as_float(p & 0xFFFF0000u); }

__device__ __forceinline__ void ldmx4(uint32_t* r, uint32_t addr) {
    asm volatile("ldmatrix.sync.aligned.m8n8.x4.shared.b16 {%0,%1,%2,%3}, [%4];"
                 : "=r"(r[0]), "=r"(r[1]), "=r"(r[2]), "=r"(r[3]) : "r"(addr));
}
__device__ __forceinline__ void ldmx2(uint32_t* r, uint32_t addr) {
    asm volatile("ldmatrix.sync.aligned.m8n8.x2.shared.b16 {%0,%1}, [%2];"
                 : "=r"(r[0]), "=r"(r[1]) : "r"(addr));
}
__device__ __forceinline__ void mma16816(float* d, const uint32_t* a, const uint32_t* b) {
    asm volatile("mma.sync.aligned.m16n8k16.row.col.f32.bf16.bf16.f32 "
                 "{%0,%1,%2,%3}, {%4,%5,%6,%7}, {%8,%9}, {%0,%1,%2,%3};"
                 : "+f"(d[0]), "+f"(d[1]), "+f"(d[2]), "+f"(d[3])
                 : "r"(a[0]), "r"(a[1]), "r"(a[2]), "r"(a[3]), "r"(b[0]), "r"(b[1]));
}

// ---------------- init / degree / norms ----------------
__global__ void init_zero_kernel(int n) {
    int i = blockIdx.x * blockDim.x + threadIdx.x;
    if (i < n) g_cnt[i] = 0;
    if (i < 2 * DIM) g_stats[i] = 0.f;
}
__global__ void deg_kernel(const int* __restrict__ col, int E) {
    int e = blockIdx.x * blockDim.x + threadIdx.x;
    if (e < E) atomicAdd(&g_cnt[col[e]], 1);
}
__global__ void node_prep_kernel(int n) {
    int i = blockIdx.x * blockDim.x + threadIdx.x;
    if (i < n) {
        float d = (float)g_cnt[i];
        g_deg_inv[i] = 1.0f / fmaxf(d, 1.0f);
        g_dis[i] = rsqrtf(d + 1.0f);
    }
}

// ---------------- prefix scan (3 kernels) ----------------
__global__ void scan1_kernel(int N) {
    __shared__ int sh[256];
    int b = blockIdx.x, t = threadIdx.x;
    int base = b * 1024 + t * 4;
    int s = 0;
#pragma unroll
    for (int q = 0; q < 4; q++) { int idx = base + q; if (idx < N) s += g_cnt[idx]; }
    sh[t] = s; __syncthreads();
    for (int st = 128; st > 0; st >>= 1) {
        if (t < st) sh[t] += sh[t + st];
        __syncthreads();
    }
    if (t == 0) g_bsum[b] = sh[0];
}
__global__ void scan2_kernel(int nb) {
    __shared__ int sh[64];
    int t = threadIdx.x;
    int own = (t < nb) ? g_bsum[t] : 0;
    sh[t] = own; __syncthreads();
    for (int st = 1; st < 64; st <<= 1) {
        int add = (t >= st) ? sh[t - st] : 0;
        __syncthreads();
        sh[t] += add;
        __syncthreads();
    }
    if (t < nb) g_boff[t] = sh[t] - own;
}
__global__ void scan3_kernel(int N, int E) {
    __shared__ int sh[256];
    int b = blockIdx.x, t = threadIdx.x;
    int base = b * 1024 + t * 4;
    int v[4]; int s = 0;
#pragma unroll
    for (int q = 0; q < 4; q++) { int idx = base + q; v[q] = (idx < N) ? g_cnt[idx] : 0; s += v[q]; }
    sh[t] = s; __syncthreads();
    for (int st = 1; st < 256; st <<= 1) {
        int add = (t >= st) ? sh[t - st] : 0;
        __syncthreads();
        sh[t] += add;
        __syncthreads();
    }
    int run = sh[t] - s + g_boff[b];
#pragma unroll
    for (int q = 0; q < 4; q++) {
        int idx = base + q;
        if (idx < N) { g_start[idx] = run; g_cursor[idx] = run; run += v[q]; }
    }
    if (b == 0 && t == 0) g_start[N] = E;
}
__global__ void fill_kernel(const int* __restrict__ edge, int E) {
    int e = blockIdx.x * blockDim.x + threadIdx.x;
    if (e < E) {
        int r = __ldg(edge + e);
        int c = __ldg(edge + E + e);
        int pos = atomicAdd(&g_cursor[c], 1);
        g_src[pos] = r;
    }
}

// ---------------- B prep: weights -> bf16 split (row-major) ----------------
__global__ void bprep_kernel(const float* __restrict__ W_out, const float* __restrict__ W_root,
                             const float* __restrict__ W_sg1, const float* __restrict__ W_sg2) {
    int t = blockIdx.x * blockDim.x + threadIdx.x;  // 4 * 8192
    if (t >= 4 * 8192) return;
    int sel = t >> 13;
    int rem = t & 8191;
    int n = rem >> 6;
    int k = (rem & 63) << 1;
    const float* W = (sel == 0) ? W_out : (sel == 1) ? W_root : (sel == 2) ? W_sg1 : W_sg2;
    float x = __ldg(W + n * 128 + k);
    float y = __ldg(W + n * 128 + k + 1);
    uint32_t p = bf16pair(x, y);
    uint32_t q = bf16pair(x - lo_f(p), y - hi_f(p));
    g_bhi[sel][rem] = p;
    g_blo[sel][rem] = q;
}

__device__ __forceinline__ void write_split4(uint32_t* hi, uint32_t* lo, int idx2, float4 v) {
    uint32_t p0 = bf16pair(v.x, v.y);
    uint32_t p1 = bf16pair(v.z, v.w);
    uint32_t q0 = bf16pair(v.x - lo_f(p0), v.y - hi_f(p0));
    uint32_t q1 = bf16pair(v.z - lo_f(p1), v.w - hi_f(p1));
    reinterpret_cast<uint2*>(hi)[idx2] = make_uint2(p0, p1);
    reinterpret_cast<uint2*>(lo)[idx2] = make_uint2(q0, q1);
}

// ---------------- gather: one warp per node; writes bf16 split A rows ----------------
// SRC=0 (layer 0): cols 0..127 = deg_inv[n]*sum(emb[x_idx[r]]); cols 128..255 = emb[x_idx[n]]
// SRC=1 (SGConv):  z[r] = dis[r]*relu(bn(h[r])) computed INLINE from g_h + g_bnp;
//                  cols 0..127 = dis[n]*(sum z[r] + z[n])
template <int SRC>
__global__ void gather_kernel(const float* __restrict__ emb,
                              const int* __restrict__ x_idx, int N) {
    int t = blockIdx.x * blockDim.x + threadIdx.x;
    int n = t >> 5;
    if (n >= N) return;
    int lane = t & 31;
    int s = __ldg(&g_start[n]);
    int e = __ldg(&g_start[n + 1]);

    float4 bsc = make_float4(0.f, 0.f, 0.f, 0.f);
    float4 bsh = make_float4(0.f, 0.f, 0.f, 0.f);
    if (SRC == 1) {
        bsc = __ldg(reinterpret_cast<const float4*>(g_bnp) + lane);
        bsh = __ldg(reinterpret_cast<const float4*>(g_bnp) + 32 + lane);
    }

    float4 a0 = make_float4(0.f, 0.f, 0.f, 0.f);
    float4 a1 = make_float4(0.f, 0.f, 0.f, 0.f);
    int i = s;
    for (; i + 2 <= e; i += 2) {
        int r0 = __ldg(&g_src[i]);
        int r1 = __ldg(&g_src[i + 1]);
        if (SRC == 0) {
            const float* p0 = emb + (size_t)__ldg(x_idx + r0) * DIM;
            const float* p1 = emb + (size_t)__ldg(x_idx + r1) * DIM;
            float4 v0 = __ldg(reinterpret_cast<const float4*>(p0) + lane);
            float4 v1 = __ldg(reinterpret_cast<const float4*>(p1) + lane);
            a0.x += v0.x; a0.y += v0.y; a0.z += v0.z; a0.w += v0.w;
            a1.x += v1.x; a1.y += v1.y; a1.z += v1.z; a1.w += v1.w;
        } else {
            float d0 = __ldg(&g_dis[r0]);
            float d1 = __ldg(&g_dis[r1]);
            float4 h0 = __ldg(reinterpret_cast<const float4*>(g_h + (size_t)r0 * DIM) + lane);
            float4 h1 = __ldg(reinterpret_cast<const float4*>(g_h + (size_t)r1 * DIM) + lane);
            a0.x += d0 * fmaxf(fmaf(h0.x, bsc.x, bsh.x), 0.f);
            a0.y += d0 * fmaxf(fmaf(h0.y, bsc.y, bsh.y), 0.f);
            a0.z += d0 * fmaxf(fmaf(h0.z, bsc.z, bsh.z), 0.f);
            a0.w += d0 * fmaxf(fmaf(h0.w, bsc.w, bsh.w), 0.f);
            a1.x += d1 * fmaxf(fmaf(h1.x, bsc.x, bsh.x), 0.f);
            a1.y += d1 * fmaxf(fmaf(h1.y, bsc.y, bsh.y), 0.f);
            a1.z += d1 * fmaxf(fmaf(h1.z, bsc.z, bsh.z), 0.f);
            a1.w += d1 * fmaxf(fmaf(h1.w, bsc.w, bsh.w), 0.f);
        }
    }
    if (i < e) {
        int r0 = __ldg(&g_src[i]);
        if (SRC == 0) {
            const float* p0 = emb + (size_t)__ldg(x_idx + r0) * DIM;
            float4 v0 = __ldg(reinterpret_cast<const float4*>(p0) + lane);
            a0.x += v0.x; a0.y += v0.y; a0.z += v0.z; a0.w += v0.w;
        } else {
            float d0 = __ldg(&g_dis[r0]);
            float4 h0 = __ldg(reinterpret_cast<const float4*>(g_h + (size_t)r0 * DIM) + lane);
            a0.x += d0 * fmaxf(fmaf(h0.x, bsc.x, bsh.x), 0.f);
            a0.y += d0 * fmaxf(fmaf(h0.y, bsc.y, bsh.y), 0.f);
            a0.z += d0 * fmaxf(fmaf(h0.z, bsc.z, bsh.z), 0.f);
            a0.w += d0 * fmaxf(fmaf(h0.w, bsc.w, bsh.w), 0.f);
        }
    }
    a0.x += a1.x; a0.y += a1.y; a0.z += a1.z; a0.w += a1.w;

    uint32_t* Ah = g_ahi + (size_t)n * 128;
    uint32_t* Al = g_alo + (size_t)n * 128;

    if (SRC == 0) {
        float sc = g_deg_inv[n];
        write_split4(Ah, Al, lane,
                     make_float4(sc * a0.x, sc * a0.y, sc * a0.z, sc * a0.w));
        const float* pr = emb + (size_t)__ldg(x_idx + n) * DIM;
        float4 vr = __ldg(reinterpret_cast<const float4*>(pr) + lane);
        write_split4(Ah, Al, 32 + lane, vr);
    } else {
        float dn = g_dis[n];
        float4 hn = __ldg(reinterpret_cast<const float4*>(g_h + (size_t)n * DIM) + lane);
        float4 zn;
        zn.x = dn * fmaxf(fmaf(hn.x, bsc.x, bsh.x), 0.f);
        zn.y = dn * fmaxf(fmaf(hn.y, bsc.y, bsh.y), 0.f);
        zn.z = dn * fmaxf(fmaf(hn.z, bsc.z, bsh.z), 0.f);
        zn.w = dn * fmaxf(fmaf(hn.w, bsc.w, bsh.w), 0.f);
        write_split4(Ah, Al, lane,
                     make_float4(dn * (a0.x + zn.x), dn * (a0.y + zn.y),
                                 dn * (a0.z + zn.z), dn * (a0.w + zn.w)));
    }
}

// ---------------- mma.sync GEMM: 128x128 tile per block, bf16 3-term split ----------------
// smem rows padded to 17 x 16B (272B) -> conflict-free ldmatrix
#define SROW 272
#define OFF_AHI 0
#define OFF_ALO 34816
#define OFF_BHI 69632
#define OFF_BLO 104448
#define SMEM_BYTES 139264

template <int KCHUNKS, bool STATS, bool BIAS>
__global__ __launch_bounds__(256, 1)
void mma_kernel(const float* __restrict__ bias, float* __restrict__ H, int N, int bsel) {
    extern __shared__ __align__(16) char smem[];
    __shared__ float sstats[256];

    const int tid = threadIdx.x;
    const int wid = tid >> 5;
    const int lane = tid & 31;
    const int tile = blockIdx.x;
    const int warpRow = wid & 3;        // 4 row groups of 32
    const int warpCol = wid >> 2;       // 2 col groups of 64

    sstats[tid] = 0.f;

    const uint32_t smemu = smem_u32(smem);

    float acc[2][8][4];
#pragma unroll
    for (int mt = 0; mt < 2; mt++)
#pragma unroll
        for (int nt = 0; nt < 8; nt++)
#pragma unroll
            for (int q = 0; q < 4; q++) acc[mt][nt][q] = 0.f;

    uint32_t aAddr[2][2];   // [mt][hi/lo]
#pragma unroll
    for (int mt = 0; mt < 2; mt++) {
        uint32_t rb = (uint32_t)(warpRow * 32 + mt * 16 + (lane & 15)) * SROW + ((lane >> 4) << 4);
        aAddr[mt][0] = smemu + OFF_AHI + rb;
        aAddr[mt][1] = smemu + OFF_ALO + rb;
    }
    uint32_t bRow = (uint32_t)(warpCol * 64 + (lane & 7)) * SROW + (((lane >> 3) & 1) << 4);
    uint32_t bAddrHi = smemu + OFF_BHI + bRow;
    uint32_t bAddrLo = smemu + OFF_BLO + bRow;

#pragma unroll
    for (int c = 0; c < KCHUNKS; c++) {
        __syncthreads();
        {
            const int4* gAh = (const int4*)(g_ahi + ((size_t)tile * 128) * 128) + c * 16;
            const int4* gAl = (const int4*)(g_alo + ((size_t)tile * 128) * 128) + c * 16;
            const int4* gBh = (const int4*)(g_bhi[bsel + c]);
            const int4* gBl = (const int4*)(g_blo[bsel + c]);
            int4* sAh = (int4*)(smem + OFF_AHI);
            int4* sAl = (int4*)(smem + OFF_ALO);
            int4* sBh = (int4*)(smem + OFF_BHI);
            int4* sBl = (int4*)(smem + OFF_BLO);
#pragma unroll
            for (int it = 0; it < 8; it++) {
                int idx = tid + it * 256;           // 0..2047
                int r = idx >> 4;
                int ch = idx & 15;
                int sIdx = r * 17 + ch;
                sAh[sIdx] = __ldg(gAh + r * 32 + ch);   // A global row stride 512B = 32 int4
                sAl[sIdx] = __ldg(gAl + r * 32 + ch);
                sBh[sIdx] = __ldg(gBh + r * 16 + ch);   // B global row stride 256B = 16 int4
                sBl[sIdx] = __ldg(gBl + r * 16 + ch);
            }
        }
        __syncthreads();

#pragma unroll
        for (int ks = 0; ks < 8; ks++) {
            uint32_t ahi[2][4], alo[2][4];
#pragma unroll
            for (int mt = 0; mt < 2; mt++) {
                ldmx4(ahi[mt], aAddr[mt][0] + ks * 32);
                ldmx4(alo[mt], aAddr[mt][1] + ks * 32);
            }
#pragma unroll
            for (int nt = 0; nt < 8; nt++) {
                uint32_t bhi[2], blo[2];
                ldmx2(bhi, bAddrHi + nt * (8 * SROW) + ks * 32);
                ldmx2(blo, bAddrLo + nt * (8 * SROW) + ks * 32);
#pragma unroll
                for (int mt = 0; mt < 2; mt++) {
                    mma16816(acc[mt][nt], ahi[mt], bhi);
                    mma16816(acc[mt][nt], ahi[mt], blo);
                    mma16816(acc[mt][nt], alo[mt], bhi);
                }
            }
        }
    }

    // ---- epilogue: bias + store + BN stats ----
    const int rowbase = tile * 128 + warpRow * 32;
    const int colbase = warpCol * 64;

    float s[8][2], q[8][2];
#pragma unroll
    for (int nt = 0; nt < 8; nt++) { s[nt][0] = s[nt][1] = 0.f; q[nt][0] = q[nt][1] = 0.f; }

#pragma unroll
    for (int mt = 0; mt < 2; mt++) {
        int r0 = rowbase + mt * 16 + (lane >> 2);
        int r1 = r0 + 8;
#pragma unroll
        for (int nt = 0; nt < 8; nt++) {
            int col = colbase + nt * 8 + ((lane & 3) << 1);
            float b0 = BIAS ? __ldg(bias + col) : 0.f;
            float b1 = BIAS ? __ldg(bias + col + 1) : 0.f;
            float v0 = acc[mt][nt][0] + b0;
            float v1 = acc[mt][nt][1] + b1;
            float v2 = acc[mt][nt][2] + b0;
            float v3 = acc[mt][nt][3] + b1;
            if (r0 < N) {
                *(float2*)(H + (size_t)r0 * DIM + col) = make_float2(v0, v1);
                if (STATS) {
                    s[nt][0] += v0; s[nt][1] += v1;
                    q[nt][0] += v0 * v0; q[nt][1] += v1 * v1;
                }
            }
            if (r1 < N) {
                *(float2*)(H + (size_t)r1 * DIM + col) = make_float2(v2, v3);
                if (STATS) {
                    s[nt][0] += v2; s[nt][1] += v3;
                    q[nt][0] += v2 * v2; q[nt][1] += v3 * v3;
                }
            }
        }
    }

    if (STATS) {
#pragma unroll
        for (int nt = 0; nt < 8; nt++) {
#pragma unroll
            for (int p = 0; p < 2; p++) {
                float vs = s[nt][p], vq = q[nt][p];
#pragma unroll
                for (int sh = 4; sh < 32; sh <<= 1) {
                    vs += __shfl_xor_sync(0xFFFFFFFFu, vs, sh);
                    vq += __shfl_xor_sync(0xFFFFFFFFu, vq, sh);
                }
                if (lane < 4) {
                    int col = colbase + nt * 8 + (lane << 1) + p;
                    atomicAdd(&sstats[col], vs);
                    atomicAdd(&sstats[128 + col], vq);
                }
            }
        }
        __syncthreads();
        atomicAdd(&g_stats[tid], sstats[tid]);
    }
}

// ---------------- BN finalize: compute scale/shift, reset stats ----------------
__global__ void bn_finalize_kernel(const float* __restrict__ gamma,
                                   const float* __restrict__ beta, int N) {
    int c = threadIdx.x;
    if (c < DIM) {
        float invn = 1.0f / (float)N;
        float mu = g_stats[c] * invn;
        float var = fmaxf(g_stats[DIM + c] * invn - mu * mu, 0.f);
        float scale = __ldg(gamma + c) * rsqrtf(var + BN_EPS);
        g_bnp[c] = scale;
        g_bnp[DIM + c] = __ldg(beta + c) - mu * scale;
        g_stats[c] = 0.f;
        g_stats[DIM + c] = 0.f;
    }
}

// ---------------- launch ----------------
extern "C" void kernel_launch(void* const* d_in, const int* in_sizes, int n_in,
                              void* d_out, int out_size) {
    const int*   x_idx  = (const int*)d_in[0];
    const int*   edge   = (const int*)d_in[1];
    const float* emb    = (const float*)d_in[2];
    const float* W_out  = (const float*)d_in[3];
    const float* W_root = (const float*)d_in[4];
    const float* bn0_g  = (const float*)d_in[5];
    const float* bn0_b  = (const float*)d_in[6];
    const float* W_sg1  = (const float*)d_in[7];
    const float* b_sg1  = (const float*)d_in[8];
    const float* bn1_g  = (const float*)d_in[9];
    const float* bn1_b  = (const float*)d_in[10];
    const float* W_sg2  = (const float*)d_in[11];
    const float* b_sg2  = (const float*)d_in[12];
    float* out = (float*)d_out;

    int N = in_sizes[0];
    int E = in_sizes[1] / 2;

    void* hp = nullptr;
    cudaGetSymbolAddress(&hp, g_h);
    float* Hbuf = (float*)hp;

    cudaFuncSetAttribute(mma_kernel<2, true, false>, cudaFuncAttributeMaxDynamicSharedMemorySize, SMEM_BYTES);
    cudaFuncSetAttribute(mma_kernel<1, true, true>,  cudaFuncAttributeMaxDynamicSharedMemorySize, SMEM_BYTES);
    cudaFuncSetAttribute(mma_kernel<1, false, true>, cudaFuncAttributeMaxDynamicSharedMemorySize, SMEM_BYTES);

    const int nbNode = (N + 255) / 256;
    const int nbEdgeT = (E + 255) / 256;
    const int nbGath = (N * 32 + 255) / 256;
    const int nbScan = (N + 1023) / 1024;
    const int NT = (N + 127) / 128;

    // CSR build + norms + weight images
    init_zero_kernel<<<nbNode, 256>>>(N);
    deg_kernel<<<nbEdgeT, 256>>>(edge + E, E);
    scan1_kernel<<<nbScan, 256>>>(N);
    scan2_kernel<<<1, 64>>>(nbScan);
    scan3_kernel<<<nbScan, 256>>>(N, E);
    node_prep_kernel<<<nbNode, 256>>>(N);
    fill_kernel<<<nbEdgeT, 256>>>(edge, E);
    bprep_kernel<<<128, 256>>>(W_out, W_root, W_sg1, W_sg2);

    // layer 0: ClusterGCN -> (BN params)
    gather_kernel<0><<<nbGath, 256>>>(emb, x_idx, N);
    mma_kernel<2, true, false><<<NT, 256, SMEM_BYTES>>>(nullptr, Hbuf, N, 0);
    bn_finalize_kernel<<<1, 128>>>(bn0_g, bn0_b, N);

    // layer 1: SGConv (BN+ReLU applied inline in gather) -> (BN params)
    gather_kernel<1><<<nbGath, 256>>>(emb, x_idx, N);
    mma_kernel<1, true, true><<<NT, 256, SMEM_BYTES>>>(b_sg1, Hbuf, N, 2);
    bn_finalize_kernel<<<1, 128>>>(bn1_g, bn1_b, N);

    // layer 2: final SGConv (BN+ReLU inline) -> d_out
    gather_kernel<1><<<nbGath, 256>>>(emb, x_idx, N);
    mma_kernel<1, false, true><<<NT, 256, SMEM_BYTES>>>(b_sg2, out, N, 3);
}

// round 11
// speedup vs baseline: 1.8052x; 1.0604x over previous
#include <cuda_runtime.h>
#include <cuda_bf16.h>
#include <cstdint>

#define NMAX 50000
#define NPAD 50048          // 391 tiles * 128 rows
#define EMAX 600000
#define DIM 128
#define BN_EPS 1e-5f

// ---------------- device scratch (no allocations allowed) ----------------
__device__ int   g_cnt[NMAX];
__device__ int   g_start[NMAX + 1];
__device__ int   g_cursor[NMAX];
__device__ int   g_src[EMAX];
__device__ int   g_bsum[64];
__device__ float g_deg_inv[NMAX];
__device__ float g_dis[NMAX];
__device__ __align__(16) float g_h[NMAX * DIM];      // GEMM output (fp32)
__device__ __align__(16) float g_z[NMAX * DIM];      // dis * relu(bn(h)) for next gather
__device__ float g_stats[2 * DIM];
__device__ float g_bnp[2 * DIM];

// bf16 split images, row-major. A: [NPAD][256 bf16] (=128 u32). Layers 1/2 use cols 0..127.
__device__ __align__(16) uint32_t g_ahi[(size_t)NPAD * 128];
__device__ __align__(16) uint32_t g_alo[(size_t)NPAD * 128];
// B: [sel][128 n][128 k] bf16 = 8192 u32. sel: 0=W_out 1=W_root 2=W_sg1 3=W_sg2
__device__ __align__(16) uint32_t g_bhi[4][8192];
__device__ __align__(16) uint32_t g_blo[4][8192];

// ---------------- helpers ----------------
__device__ __forceinline__ uint32_t smem_u32(const void* p) {
    uint32_t a;
    asm("{ .reg .u64 t; cvta.to.shared.u64 t, %1; cvt.u32.u64 %0, t; }" : "=r"(a) : "l"(p));
    return a;
}
// pack two floats to bf16x2 (low half = first arg)
__device__ __forceinline__ uint32_t bf16pair(float lo, float hi) {
    uint32_t r;
    asm("cvt.rn.bf16x2.f32 %0, %1, %2;" : "=r"(r) : "f"(hi), "f"(lo));
    return r;
}
__device__ __forceinline__ float lo_f(uint32_t p) { return __uint_as_float(p << 16); }
__device__ __forceinline__ float hi_f(uint32_t p) { return __uint_as_float(p & 0xFFFF0000u); }

__device__ __forceinline__ void ldmx4(uint32_t* r, uint32_t addr) {
    asm volatile("ldmatrix.sync.aligned.m8n8.x4.shared.b16 {%0,%1,%2,%3}, [%4];"
                 : "=r"(r[0]), "=r"(r[1]), "=r"(r[2]), "=r"(r[3]) : "r"(addr));
}
__device__ __forceinline__ void ldmx2(uint32_t* r, uint32_t addr) {
    asm volatile("ldmatrix.sync.aligned.m8n8.x2.shared.b16 {%0,%1}, [%2];"
                 : "=r"(r[0]), "=r"(r[1]) : "r"(addr));
}
__device__ __forceinline__ void mma16816(float* d, const uint32_t* a, const uint32_t* b) {
    asm volatile("mma.sync.aligned.m16n8k16.row.col.f32.bf16.bf16.f32 "
                 "{%0,%1,%2,%3}, {%4,%5,%6,%7}, {%8,%9}, {%0,%1,%2,%3};"
                 : "+f"(d[0]), "+f"(d[1]), "+f"(d[2]), "+f"(d[3])
                 : "r"(a[0]), "r"(a[1]), "r"(a[2]), "r"(a[3]), "r"(b[0]), "r"(b[1]));
}

// ---------------- init / degree ----------------
__global__ void init_zero_kernel(int n) {
    int i = blockIdx.x * blockDim.x + threadIdx.x;
    if (i < n) g_cnt[i] = 0;
    if (i < 2 * DIM) g_stats[i] = 0.f;
}
__global__ void deg_kernel(const int* __restrict__ col, int E) {
    int e = blockIdx.x * blockDim.x + threadIdx.x;
    if (e < E) atomicAdd(&g_cnt[col[e]], 1);
}

// ---------------- prefix scan (2 kernels) ----------------
__global__ void scan1_kernel(int N) {
    __shared__ int sh[256];
    int b = blockIdx.x, t = threadIdx.x;
    int base = b * 1024 + t * 4;
    int s = 0;
#pragma unroll
    for (int q = 0; q < 4; q++) { int idx = base + q; if (idx < N) s += g_cnt[idx]; }
    sh[t] = s; __syncthreads();
    for (int st = 128; st > 0; st >>= 1) {
        if (t < st) sh[t] += sh[t + st];
        __syncthreads();
    }
    if (t == 0) g_bsum[b] = sh[0];
}
// scan3: computes its own block offset from g_bsum (<=64 blocks), writes offsets,
// cursors, and node norms (deg_inv / dis). All accesses coalesced.
__global__ void scan3_kernel(int N, int E) {
    __shared__ int sh[256];
    __shared__ int sboff[32];
    int b = blockIdx.x, t = threadIdx.x;

    // exclusive offset of this block = sum of g_bsum[0..b)
    if (t < 32) {
        int v0 = (t < b) ? g_bsum[t] : 0;
        int v1 = (t + 32 < b) ? g_bsum[t + 32] : 0;
        int v = v0 + v1;
#pragma unroll
        for (int d = 16; d > 0; d >>= 1)
            v += __shfl_down_sync(0xFFFFFFFFu, v, d);
        if (t == 0) sboff[0] = v;
    }

    int base = b * 1024 + t * 4;
    int v[4]; int s = 0;
#pragma unroll
    for (int q = 0; q < 4; q++) { int idx = base + q; v[q] = (idx < N) ? g_cnt[idx] : 0; s += v[q]; }
    sh[t] = s; __syncthreads();
    for (int st = 1; st < 256; st <<= 1) {
        int add = (t >= st) ? sh[t - st] : 0;
        __syncthreads();
        sh[t] += add;
        __syncthreads();
    }
    int run = sh[t] - s + sboff[0];
#pragma unroll
    for (int q = 0; q < 4; q++) {
        int idx = base + q;
        if (idx < N) {
            g_start[idx] = run;
            g_cursor[idx] = run;
            run += v[q];
            float d = (float)v[q];
            g_deg_inv[idx] = 1.0f / fmaxf(d, 1.0f);
            g_dis[idx] = rsqrtf(d + 1.0f);
        }
    }
    if (b == 0 && t == 0) g_start[N] = E;
}
__global__ void fill_kernel(const int* __restrict__ edge, int E) {
    int e = blockIdx.x * blockDim.x + threadIdx.x;
    if (e < E) {
        int r = __ldg(edge + e);
        int c = __ldg(edge + E + e);
        int pos = atomicAdd(&g_cursor[c], 1);
        g_src[pos] = r;
    }
}

// ---------------- B prep: weights -> bf16 split (row-major) ----------------
__global__ void bprep_kernel(const float* __restrict__ W_out, const float* __restrict__ W_root,
                             const float* __restrict__ W_sg1, const float* __restrict__ W_sg2) {
    int t = blockIdx.x * blockDim.x + threadIdx.x;  // 4 * 8192
    if (t >= 4 * 8192) return;
    int sel = t >> 13;
    int rem = t & 8191;
    int n = rem >> 6;
    int k = (rem & 63) << 1;
    const float* W = (sel == 0) ? W_out : (sel == 1) ? W_root : (sel == 2) ? W_sg1 : W_sg2;
    float x = __ldg(W + n * 128 + k);
    float y = __ldg(W + n * 128 + k + 1);
    uint32_t p = bf16pair(x, y);
    uint32_t q = bf16pair(x - lo_f(p), y - hi_f(p));
    g_bhi[sel][rem] = p;
    g_blo[sel][rem] = q;
}

__device__ __forceinline__ void write_split4(uint32_t* hi, uint32_t* lo, int idx2, float4 v) {
    uint32_t p0 = bf16pair(v.x, v.y);
    uint32_t p1 = bf16pair(v.z, v.w);
    uint32_t q0 = bf16pair(v.x - lo_f(p0), v.y - hi_f(p0));
    uint32_t q1 = bf16pair(v.z - lo_f(p1), v.w - hi_f(p1));
    reinterpret_cast<uint2*>(hi)[idx2] = make_uint2(p0, p1);
    reinterpret_cast<uint2*>(lo)[idx2] = make_uint2(q0, q1);
}

// ---------------- gather: one warp per node; writes bf16 split A rows ----------------
// SRC=0 (layer 0): cols 0..127 = deg_inv[n]*sum(emb[x_idx[r]]); cols 128..255 = emb[x_idx[n]]
// SRC=1 (SGConv):  cols 0..127 = dis[n]*(sum(g_z[r]) + g_z[n]),  z already dis-prescaled
template <int SRC>
__global__ void gather_kernel(const float* __restrict__ emb,
                              const int* __restrict__ x_idx, int N) {
    int t = blockIdx.x * blockDim.x + threadIdx.x;
    int n = t >> 5;
    if (n >= N) return;
    int lane = t & 31;
    int s = __ldg(&g_start[n]);
    int e = __ldg(&g_start[n + 1]);
    float4 a0 = make_float4(0.f, 0.f, 0.f, 0.f);
    float4 a1 = make_float4(0.f, 0.f, 0.f, 0.f);
    int i = s;
    for (; i + 2 <= e; i += 2) {
        int r0 = __ldg(&g_src[i]);
        int r1 = __ldg(&g_src[i + 1]);
        const float* p0;
        const float* p1;
        if (SRC == 0) {
            p0 = emb + (size_t)__ldg(x_idx + r0) * DIM;
            p1 = emb + (size_t)__ldg(x_idx + r1) * DIM;
        } else {
            p0 = g_z + (size_t)r0 * DIM;
            p1 = g_z + (size_t)r1 * DIM;
        }
        float4 v0 = __ldg(reinterpret_cast<const float4*>(p0) + lane);
        float4 v1 = __ldg(reinterpret_cast<const float4*>(p1) + lane);
        a0.x += v0.x; a0.y += v0.y; a0.z += v0.z; a0.w += v0.w;
        a1.x += v1.x; a1.y += v1.y; a1.z += v1.z; a1.w += v1.w;
    }
    if (i < e) {
        int r0 = __ldg(&g_src[i]);
        const float* p0 = (SRC == 0) ? emb + (size_t)__ldg(x_idx + r0) * DIM
                                     : g_z + (size_t)r0 * DIM;
        float4 v0 = __ldg(reinterpret_cast<const float4*>(p0) + lane);
        a0.x += v0.x; a0.y += v0.y; a0.z += v0.z; a0.w += v0.w;
    }
    a0.x += a1.x; a0.y += a1.y; a0.z += a1.z; a0.w += a1.w;

    uint32_t* Ah = g_ahi + (size_t)n * 128;
    uint32_t* Al = g_alo + (size_t)n * 128;

    if (SRC == 0) {
        float sc = g_deg_inv[n];
        write_split4(Ah, Al, lane,
                     make_float4(sc * a0.x, sc * a0.y, sc * a0.z, sc * a0.w));
        const float* pr = emb + (size_t)__ldg(x_idx + n) * DIM;
        float4 vr = __ldg(reinterpret_cast<const float4*>(pr) + lane);
        write_split4(Ah, Al, 32 + lane, vr);
    } else {
        float sc = g_dis[n];
        float4 z = __ldg(reinterpret_cast<const float4*>(g_z + (size_t)n * DIM) + lane);
        write_split4(Ah, Al, lane,
                     make_float4(sc * (a0.x + z.x), sc * (a0.y + z.y),
                                 sc * (a0.z + z.z), sc * (a0.w + z.w)));
    }
}

// ---------------- mma.sync GEMM: 128x128 tile per block, bf16 3-term split ----------------
// smem rows padded to 17 x 16B (272B) -> conflict-free ldmatrix
#define SROW 272
#define OFF_AHI 0
#define OFF_ALO 34816
#define OFF_BHI 69632
#define OFF_BLO 104448
#define SMEM_BYTES 139264

template <int KCHUNKS, bool STATS, bool BIAS>
__global__ __launch_bounds__(256, 1)
void mma_kernel(const float* __restrict__ bias, float* __restrict__ H, int N, int bsel) {
    extern __shared__ __align__(16) char smem[];
    __shared__ float sstats[256];

    const int tid = threadIdx.x;
    const int wid = tid >> 5;
    const int lane = tid & 31;
    const int tile = blockIdx.x;
    const int warpRow = wid & 3;        // 4 row groups of 32
    const int warpCol = wid >> 2;       // 2 col groups of 64

    sstats[tid] = 0.f;

    const uint32_t smemu = smem_u32(smem);

    float acc[2][8][4];
#pragma unroll
    for (int mt = 0; mt < 2; mt++)
#pragma unroll
        for (int nt = 0; nt < 8; nt++)
#pragma unroll
            for (int q = 0; q < 4; q++) acc[mt][nt][q] = 0.f;

    uint32_t aAddr[2][2];   // [mt][hi/lo]
#pragma unroll
    for (int mt = 0; mt < 2; mt++) {
        uint32_t rb = (uint32_t)(warpRow * 32 + mt * 16 + (lane & 15)) * SROW + ((lane >> 4) << 4);
        aAddr[mt][0] = smemu + OFF_AHI + rb;
        aAddr[mt][1] = smemu + OFF_ALO + rb;
    }
    uint32_t bRow = (uint32_t)(warpCol * 64 + (lane & 7)) * SROW + (((lane >> 3) & 1) << 4);
    uint32_t bAddrHi = smemu + OFF_BHI + bRow;
    uint32_t bAddrLo = smemu + OFF_BLO + bRow;

#pragma unroll
    for (int c = 0; c < KCHUNKS; c++) {
        __syncthreads();
        {
            const int4* gAh = (const int4*)(g_ahi + ((size_t)tile * 128) * 128) + c * 16;
            const int4* gAl = (const int4*)(g_alo + ((size_t)tile * 128) * 128) + c * 16;
            const int4* gBh = (const int4*)(g_bhi[bsel + c]);
            const int4* gBl = (const int4*)(g_blo[bsel + c]);
            int4* sAh = (int4*)(smem + OFF_AHI);
            int4* sAl = (int4*)(smem + OFF_ALO);
            int4* sBh = (int4*)(smem + OFF_BHI);
            int4* sBl = (int4*)(smem + OFF_BLO);
#pragma unroll
            for (int it = 0; it < 8; it++) {
                int idx = tid + it * 256;           // 0..2047
                int r = idx >> 4;
                int ch = idx & 15;
                int sIdx = r * 17 + ch;
                sAh[sIdx] = __ldg(gAh + r * 32 + ch);   // A global row stride 512B = 32 int4
                sAl[sIdx] = __ldg(gAl + r * 32 + ch);
                sBh[sIdx] = __ldg(gBh + r * 16 + ch);   // B global row stride 256B = 16 int4
                sBl[sIdx] = __ldg(gBl + r * 16 + ch);
            }
        }
        __syncthreads();

#pragma unroll
        for (int ks = 0; ks < 8; ks++) {
            uint32_t ahi[2][4], alo[2][4];
#pragma unroll
            for (int mt = 0; mt < 2; mt++) {
                ldmx4(ahi[mt], aAddr[mt][0] + ks * 32);
                ldmx4(alo[mt], aAddr[mt][1] + ks * 32);
            }
#pragma unroll
            for (int nt = 0; nt < 8; nt++) {
                uint32_t bhi[2], blo[2];
                ldmx2(bhi, bAddrHi + nt * (8 * SROW) + ks * 32);
                ldmx2(blo, bAddrLo + nt * (8 * SROW) + ks * 32);
#pragma unroll
                for (int mt = 0; mt < 2; mt++) {
                    mma16816(acc[mt][nt], ahi[mt], bhi);
                    mma16816(acc[mt][nt], ahi[mt], blo);
                    mma16816(acc[mt][nt], alo[mt], bhi);
                }
            }
        }
    }

    // ---- epilogue: bias + store + BN stats ----
    const int rowbase = tile * 128 + warpRow * 32;
    const int colbase = warpCol * 64;

    float s[8][2], q[8][2];
#pragma unroll
    for (int nt = 0; nt < 8; nt++) { s[nt][0] = s[nt][1] = 0.f; q[nt][0] = q[nt][1] = 0.f; }

#pragma unroll
    for (int mt = 0; mt < 2; mt++) {
        int r0 = rowbase + mt * 16 + (lane >> 2);
        int r1 = r0 + 8;
#pragma unroll
        for (int nt = 0; nt < 8; nt++) {
            int col = colbase + nt * 8 + ((lane & 3) << 1);
            float b0 = BIAS ? __ldg(bias + col) : 0.f;
            float b1 = BIAS ? __ldg(bias + col + 1) : 0.f;
            float v0 = acc[mt][nt][0] + b0;
            float v1 = acc[mt][nt][1] + b1;
            float v2 = acc[mt][nt][2] + b0;
            float v3 = acc[mt][nt][3] + b1;
            if (r0 < N) {
                *(float2*)(H + (size_t)r0 * DIM + col) = make_float2(v0, v1);
                if (STATS) {
                    s[nt][0] += v0; s[nt][1] += v1;
                    q[nt][0] += v0 * v0; q[nt][1] += v1 * v1;
                }
            }
            if (r1 < N) {
                *(float2*)(H + (size_t)r1 * DIM + col) = make_float2(v2, v3);
                if (STATS) {
                    s[nt][0] += v2; s[nt][1] += v3;
                    q[nt][0] += v2 * v2; q[nt][1] += v3 * v3;
                }
            }
        }
    }

    if (STATS) {
#pragma unroll
        for (int nt = 0; nt < 8; nt++) {
#pragma unroll
            for (int p = 0; p < 2; p++) {
                float vs = s[nt][p], vq = q[nt][p];
#pragma unroll
                for (int sh = 4; sh < 32; sh <<= 1) {
                    vs += __shfl_xor_sync(0xFFFFFFFFu, vs, sh);
                    vq += __shfl_xor_sync(0xFFFFFFFFu, vq, sh);
                }
                if (lane < 4) {
                    int col = colbase + nt * 8 + (lane << 1) + p;
                    atomicAdd(&sstats[col], vs);
                    atomicAdd(&sstats[128 + col], vq);
                }
            }
        }
        __syncthreads();
        atomicAdd(&g_stats[tid], sstats[tid]);
    }
}

// ---------------- BN finalize ----------------
__global__ void bn_finalize_kernel(const float* __restrict__ gamma,
                                   const float* __restrict__ beta, int N) {
    int c = threadIdx.x;
    if (c < DIM) {
        float invn = 1.0f / (float)N;
        float mu = g_stats[c] * invn;
        float var = fmaxf(g_stats[DIM + c] * invn - mu * mu, 0.f);
        float scale = __ldg(gamma + c) * rsqrtf(var + BN_EPS);
        g_bnp[c] = scale;
        g_bnp[DIM + c] = __ldg(beta + c) - mu * scale;
        g_stats[c] = 0.f;
        g_stats[DIM + c] = 0.f;
    }
}

// ---------------- BN apply + ReLU + dis-prescale (z = dis * relu(bn(h))) ----------------
__global__ void bn_apply_kernel(int N) {
    int i = blockIdx.x * blockDim.x + threadIdx.x;
    int tot = N * (DIM / 4);
    if (i >= tot) return;
    int n = i >> 5;
    int q = i & 31;
    float4 h = reinterpret_cast<const float4*>(g_h)[i];
    float4 sc = reinterpret_cast<const float4*>(g_bnp)[q];
    float4 sh = reinterpret_cast<const float4*>(g_bnp + DIM)[q];
    float d = g_dis[n];
    float4 z;
    z.x = d * fmaxf(fmaf(h.x, sc.x, sh.x), 0.f);
    z.y = d * fmaxf(fmaf(h.y, sc.y, sh.y), 0.f);
    z.z = d * fmaxf(fmaf(h.z, sc.z, sh.z), 0.f);
    z.w = d * fmaxf(fmaf(h.w, sc.w, sh.w), 0.f);
    reinterpret_cast<float4*>(g_z)[i] = z;
}

// ---------------- launch ----------------
extern "C" void kernel_launch(void* const* d_in, const int* in_sizes, int n_in,
                              void* d_out, int out_size) {
    const int*   x_idx  = (const int*)d_in[0];
    const int*   edge   = (const int*)d_in[1];
    const float* emb    = (const float*)d_in[2];
    const float* W_out  = (const float*)d_in[3];
    const float* W_root = (const float*)d_in[4];
    const float* bn0_g  = (const float*)d_in[5];
    const float* bn0_b  = (const float*)d_in[6];
    const float* W_sg1  = (const float*)d_in[7];
    const float* b_sg1  = (const float*)d_in[8];
    const float* bn1_g  = (const float*)d_in[9];
    const float* bn1_b  = (const float*)d_in[10];
    const float* W_sg2  = (const float*)d_in[11];
    const float* b_sg2  = (const float*)d_in[12];
    float* out = (float*)d_out;

    int N = in_sizes[0];
    int E = in_sizes[1] / 2;

    void* hp = nullptr;
    cudaGetSymbolAddress(&hp, g_h);
    float* Hbuf = (float*)hp;

    cudaFuncSetAttribute(mma_kernel<2, true, false>, cudaFuncAttributeMaxDynamicSharedMemorySize, SMEM_BYTES);
    cudaFuncSetAttribute(mma_kernel<1, true, true>,  cudaFuncAttributeMaxDynamicSharedMemorySize, SMEM_BYTES);
    cudaFuncSetAttribute(mma_kernel<1, false, true>, cudaFuncAttributeMaxDynamicSharedMemorySize, SMEM_BYTES);

    const int nbElem = (N * (DIM / 4) + 255) / 256;
    const int nbNode = (N + 255) / 256;
    const int nbEdgeT = (E + 255) / 256;
    const int nbGath = (N * 32 + 255) / 256;
    const int nbScan = (N + 1023) / 1024;
    const int NT = (N + 127) / 128;

    // CSR build + norms + weight images
    init_zero_kernel<<<nbNode, 256>>>(N);
    deg_kernel<<<nbEdgeT, 256>>>(edge + E, E);
    scan1_kernel<<<nbScan, 256>>>(N);
    scan3_kernel<<<nbScan, 256>>>(N, E);
    fill_kernel<<<nbEdgeT, 256>>>(edge, E);
    bprep_kernel<<<128, 256>>>(W_out, W_root, W_sg1, W_sg2);

    // layer 0: ClusterGCN -> BN -> ReLU
    gather_kernel<0><<<nbGath, 256>>>(emb, x_idx, N);
    mma_kernel<2, true, false><<<NT, 256, SMEM_BYTES>>>(nullptr, Hbuf, N, 0);
    bn_finalize_kernel<<<1, 128>>>(bn0_g, bn0_b, N);
    bn_apply_kernel<<<nbElem, 256>>>(N);

    // layer 1: SGConv -> BN -> ReLU
    gather_kernel<1><<<nbGath, 256>>>(emb, x_idx, N);
    mma_kernel<1, true, true><<<NT, 256, SMEM_BYTES>>>(b_sg1, Hbuf, N, 2);
    bn_finalize_kernel<<<1, 128>>>(bn1_g, bn1_b, N);
    bn_apply_kernel<<<nbElem, 256>>>(N);

    // layer 2: final SGConv -> d_out
    gather_kernel<1><<<nbGath, 256>>>(emb, x_idx, N);
    mma_kernel<1, false, true><<<NT, 256, SMEM_BYTES>>>(b_sg2, out, N, 3);
}

// round 12
// speedup vs baseline: 1.8234x; 1.0100x over previous
#include <cuda_runtime.h>
#include <cuda_bf16.h>
#include <cstdint>

#define NMAX 50000
#define NPAD 50048          // 391 tiles * 128 rows
#define EMAX 600000
#define DIM 128
#define BN_EPS 1e-5f

// ---------------- device scratch (no allocations allowed) ----------------
__device__ int   g_cnt[NMAX];
__device__ int   g_start[NMAX + 1];
__device__ int   g_cursor[NMAX];
__device__ int   g_src[EMAX];
__device__ int   g_bsum[64];
__device__ float g_deg_inv[NMAX];
__device__ float g_dis[NMAX];
__device__ __align__(16) float g_h[NMAX * DIM];      // GEMM output (fp32)
__device__ __align__(16) float g_z[NMAX * DIM];      // dis * relu(bn(h)) for next gather
__device__ __align__(16) float g_stats[2][256];      // per-BN-layer col sum / sumsq

// bf16 split images, row-major. A: [NPAD][256 bf16] (=128 u32). Layers 1/2 use cols 0..127.
__device__ __align__(16) uint32_t g_ahi[(size_t)NPAD * 128];
__device__ __align__(16) uint32_t g_alo[(size_t)NPAD * 128];
// B: [sel][128 n][128 k] bf16 = 8192 u32. sel: 0=W_out 1=W_root 2=W_sg1 3=W_sg2
__device__ __align__(16) uint32_t g_bhi[4][8192];
__device__ __align__(16) uint32_t g_blo[4][8192];

// ---------------- helpers ----------------
__device__ __forceinline__ uint32_t smem_u32(const void* p) {
    uint32_t a;
    asm("{ .reg .u64 t; cvta.to.shared.u64 t, %1; cvt.u32.u64 %0, t; }" : "=r"(a) : "l"(p));
    return a;
}
// pack two floats to bf16x2 (low half = first arg)
__device__ __forceinline__ uint32_t bf16pair(float lo, float hi) {
    uint32_t r;
    asm("cvt.rn.bf16x2.f32 %0, %1, %2;" : "=r"(r) : "f"(hi), "f"(lo));
    return r;
}
__device__ __forceinline__ float lo_f(uint32_t p) { return __uint_as_float(p << 16); }
__device__ __forceinline__ float hi_f(uint32_t p) { return __uint_as_float(p & 0xFFFF0000u); }

__device__ __forceinline__ void ldmx4(uint32_t* r, uint32_t addr) {
    asm volatile("ldmatrix.sync.aligned.m8n8.x4.shared.b16 {%0,%1,%2,%3}, [%4];"
                 : "=r"(r[0]), "=r"(r[1]), "=r"(r[2]), "=r"(r[3]) : "r"(addr));
}
__device__ __forceinline__ void ldmx2(uint32_t* r, uint32_t addr) {
    asm volatile("ldmatrix.sync.aligned.m8n8.x2.shared.b16 {%0,%1}, [%2];"
                 : "=r"(r[0]), "=r"(r[1]) : "r"(addr));
}
__device__ __forceinline__ void mma16816(float* d, const uint32_t* a, const uint32_t* b) {
    asm volatile("mma.sync.aligned.m16n8k16.row.col.f32.bf16.bf16.f32 "
                 "{%0,%1,%2,%3}, {%4,%5,%6,%7}, {%8,%9}, {%0,%1,%2,%3};"
                 : "+f"(d[0]), "+f"(d[1]), "+f"(d[2]), "+f"(d[3])
                 : "r"(a[0]), "r"(a[1]), "r"(a[2]), "r"(a[3]), "r"(b[0]), "r"(b[1]));
}

// ---------------- init ----------------
__global__ void init_zero_kernel(int n) {
    int i = blockIdx.x * blockDim.x + threadIdx.x;
    if (i < n) g_cnt[i] = 0;
    if (i < 512) ((float*)g_stats)[i] = 0.f;
}

// ---------------- degree histogram + weight-image prep (merged launch) ----------------
// blocks [0, nbEdge): degree histogram; blocks [nbEdge, nbEdge+128): bprep
__global__ void deg_bprep_kernel(const int* __restrict__ col, int E, int nbEdge,
                                 const float* __restrict__ W_out, const float* __restrict__ W_root,
                                 const float* __restrict__ W_sg1, const float* __restrict__ W_sg2) {
    if (blockIdx.x < (unsigned)nbEdge) {
        int e = blockIdx.x * blockDim.x + threadIdx.x;
        if (e < E) atomicAdd(&g_cnt[col[e]], 1);
    } else {
        int t = (blockIdx.x - nbEdge) * blockDim.x + threadIdx.x;  // 0 .. 32767
        if (t >= 4 * 8192) return;
        int sel = t >> 13;
        int rem = t & 8191;
        int n = rem >> 6;
        int k = (rem & 63) << 1;
        const float* W = (sel == 0) ? W_out : (sel == 1) ? W_root : (sel == 2) ? W_sg1 : W_sg2;
        float x = __ldg(W + n * 128 + k);
        float y = __ldg(W + n * 128 + k + 1);
        uint32_t p = bf16pair(x, y);
        uint32_t q = bf16pair(x - lo_f(p), y - hi_f(p));
        g_bhi[sel][rem] = p;
        g_blo[sel][rem] = q;
    }
}

// ---------------- prefix scan (2 kernels) ----------------
__global__ void scan1_kernel(int N) {
    __shared__ int sh[256];
    int b = blockIdx.x, t = threadIdx.x;
    int base = b * 1024 + t * 4;
    int s = 0;
#pragma unroll
    for (int q = 0; q < 4; q++) { int idx = base + q; if (idx < N) s += g_cnt[idx]; }
    sh[t] = s; __syncthreads();
    for (int st = 128; st > 0; st >>= 1) {
        if (t < st) sh[t] += sh[t + st];
        __syncthreads();
    }
    if (t == 0) g_bsum[b] = sh[0];
}
// scan3: computes its own block offset from g_bsum (<=64 blocks), writes offsets,
// cursors, and node norms (deg_inv / dis). All accesses coalesced.
__global__ void scan3_kernel(int N, int E) {
    __shared__ int sh[256];
    __shared__ int sboff[32];
    int b = blockIdx.x, t = threadIdx.x;

    if (t < 32) {
        int v0 = (t < b) ? g_bsum[t] : 0;
        int v1 = (t + 32 < b) ? g_bsum[t + 32] : 0;
        int v = v0 + v1;
#pragma unroll
        for (int d = 16; d > 0; d >>= 1)
            v += __shfl_down_sync(0xFFFFFFFFu, v, d);
        if (t == 0) sboff[0] = v;
    }

    int base = b * 1024 + t * 4;
    int v[4]; int s = 0;
#pragma unroll
    for (int q = 0; q < 4; q++) { int idx = base + q; v[q] = (idx < N) ? g_cnt[idx] : 0; s += v[q]; }
    sh[t] = s; __syncthreads();
    for (int st = 1; st < 256; st <<= 1) {
        int add = (t >= st) ? sh[t - st] : 0;
        __syncthreads();
        sh[t] += add;
        __syncthreads();
    }
    int run = sh[t] - s + sboff[0];
#pragma unroll
    for (int q = 0; q < 4; q++) {
        int idx = base + q;
        if (idx < N) {
            g_start[idx] = run;
            g_cursor[idx] = run;
            run += v[q];
            float d = (float)v[q];
            g_deg_inv[idx] = 1.0f / fmaxf(d, 1.0f);
            g_dis[idx] = rsqrtf(d + 1.0f);
        }
    }
    if (b == 0 && t == 0) g_start[N] = E;
}
__global__ void fill_kernel(const int* __restrict__ edge, int E) {
    int e = blockIdx.x * blockDim.x + threadIdx.x;
    if (e < E) {
        int r = __ldg(edge + e);
        int c = __ldg(edge + E + e);
        int pos = atomicAdd(&g_cursor[c], 1);
        g_src[pos] = r;
    }
}

__device__ __forceinline__ void write_split4(uint32_t* hi, uint32_t* lo, int idx2, float4 v) {
    uint32_t p0 = bf16pair(v.x, v.y);
    uint32_t p1 = bf16pair(v.z, v.w);
    uint32_t q0 = bf16pair(v.x - lo_f(p0), v.y - hi_f(p0));
    uint32_t q1 = bf16pair(v.z - lo_f(p1), v.w - hi_f(p1));
    reinterpret_cast<uint2*>(hi)[idx2] = make_uint2(p0, p1);
    reinterpret_cast<uint2*>(lo)[idx2] = make_uint2(q0, q1);
}

// ---------------- gather: one warp per node; writes bf16 split A rows ----------------
// SRC=0 (layer 0): cols 0..127 = deg_inv[n]*sum(emb[x_idx[r]]); cols 128..255 = emb[x_idx[n]]
// SRC=1 (SGConv):  cols 0..127 = dis[n]*(sum(g_z[r]) + g_z[n]),  z already dis-prescaled
template <int SRC>
__global__ void gather_kernel(const float* __restrict__ emb,
                              const int* __restrict__ x_idx, int N) {
    int t = blockIdx.x * blockDim.x + threadIdx.x;
    int n = t >> 5;
    if (n >= N) return;
    int lane = t & 31;
    int s = __ldg(&g_start[n]);
    int e = __ldg(&g_start[n + 1]);
    float4 a0 = make_float4(0.f, 0.f, 0.f, 0.f);
    float4 a1 = make_float4(0.f, 0.f, 0.f, 0.f);
    int i = s;
    for (; i + 2 <= e; i += 2) {
        int r0 = __ldg(&g_src[i]);
        int r1 = __ldg(&g_src[i + 1]);
        const float* p0;
        const float* p1;
        if (SRC == 0) {
            p0 = emb + (size_t)__ldg(x_idx + r0) * DIM;
            p1 = emb + (size_t)__ldg(x_idx + r1) * DIM;
        } else {
            p0 = g_z + (size_t)r0 * DIM;
            p1 = g_z + (size_t)r1 * DIM;
        }
        float4 v0 = __ldg(reinterpret_cast<const float4*>(p0) + lane);
        float4 v1 = __ldg(reinterpret_cast<const float4*>(p1) + lane);
        a0.x += v0.x; a0.y += v0.y; a0.z += v0.z; a0.w += v0.w;
        a1.x += v1.x; a1.y += v1.y; a1.z += v1.z; a1.w += v1.w;
    }
    if (i < e) {
        int r0 = __ldg(&g_src[i]);
        const float* p0 = (SRC == 0) ? emb + (size_t)__ldg(x_idx + r0) * DIM
                                     : g_z + (size_t)r0 * DIM;
        float4 v0 = __ldg(reinterpret_cast<const float4*>(p0) + lane);
        a0.x += v0.x; a0.y += v0.y; a0.z += v0.z; a0.w += v0.w;
    }
    a0.x += a1.x; a0.y += a1.y; a0.z += a1.z; a0.w += a1.w;

    uint32_t* Ah = g_ahi + (size_t)n * 128;
    uint32_t* Al = g_alo + (size_t)n * 128;

    if (SRC == 0) {
        float sc = g_deg_inv[n];
        write_split4(Ah, Al, lane,
                     make_float4(sc * a0.x, sc * a0.y, sc * a0.z, sc * a0.w));
        const float* pr = emb + (size_t)__ldg(x_idx + n) * DIM;
        float4 vr = __ldg(reinterpret_cast<const float4*>(pr) + lane);
        write_split4(Ah, Al, 32 + lane, vr);
    } else {
        float sc = g_dis[n];
        float4 z = __ldg(reinterpret_cast<const float4*>(g_z + (size_t)n * DIM) + lane);
        write_split4(Ah, Al, lane,
                     make_float4(sc * (a0.x + z.x), sc * (a0.y + z.y),
                                 sc * (a0.z + z.z), sc * (a0.w + z.w)));
    }
}

// ---------------- mma.sync GEMM: 128x128 tile per block, bf16 3-term split ----------------
// smem rows padded to 17 x 16B (272B) -> conflict-free ldmatrix
#define SROW 272
#define OFF_AHI 0
#define OFF_ALO 34816
#define OFF_BHI 69632
#define OFF_BLO 104448
#define SMEM_BYTES 139264

template <int KCHUNKS, bool STATS, bool BIAS>
__global__ __launch_bounds__(256, 1)
void mma_kernel(const float* __restrict__ bias, float* __restrict__ H,
                float* __restrict__ stats, int N, int bsel) {
    extern __shared__ __align__(16) char smem[];
    __shared__ float sstats[256];

    const int tid = threadIdx.x;
    const int wid = tid >> 5;
    const int lane = tid & 31;
    const int tile = blockIdx.x;
    const int warpRow = wid & 3;        // 4 row groups of 32
    const int warpCol = wid >> 2;       // 2 col groups of 64

    sstats[tid] = 0.f;

    const uint32_t smemu = smem_u32(smem);

    float acc[2][8][4];
#pragma unroll
    for (int mt = 0; mt < 2; mt++)
#pragma unroll
        for (int nt = 0; nt < 8; nt++)
#pragma unroll
            for (int q = 0; q < 4; q++) acc[mt][nt][q] = 0.f;

    uint32_t aAddr[2][2];   // [mt][hi/lo]
#pragma unroll
    for (int mt = 0; mt < 2; mt++) {
        uint32_t rb = (uint32_t)(warpRow * 32 + mt * 16 + (lane & 15)) * SROW + ((lane >> 4) << 4);
        aAddr[mt][0] = smemu + OFF_AHI + rb;
        aAddr[mt][1] = smemu + OFF_ALO + rb;
    }
    uint32_t bRow = (uint32_t)(warpCol * 64 + (lane & 7)) * SROW + (((lane >> 3) & 1) << 4);
    uint32_t bAddrHi = smemu + OFF_BHI + bRow;
    uint32_t bAddrLo = smemu + OFF_BLO + bRow;

#pragma unroll
    for (int c = 0; c < KCHUNKS; c++) {
        __syncthreads();
        {
            const int4* gAh = (const int4*)(g_ahi + ((size_t)tile * 128) * 128) + c * 16;
            const int4* gAl = (const int4*)(g_alo + ((size_t)tile * 128) * 128) + c * 16;
            const int4* gBh = (const int4*)(g_bhi[bsel + c]);
            const int4* gBl = (const int4*)(g_blo[bsel + c]);
            int4* sAh = (int4*)(smem + OFF_AHI);
            int4* sAl = (int4*)(smem + OFF_ALO);
            int4* sBh = (int4*)(smem + OFF_BHI);
            int4* sBl = (int4*)(smem + OFF_BLO);
#pragma unroll
            for (int it = 0; it < 8; it++) {
                int idx = tid + it * 256;           // 0..2047
                int r = idx >> 4;
                int ch = idx & 15;
                int sIdx = r * 17 + ch;
                sAh[sIdx] = __ldg(gAh + r * 32 + ch);   // A global row stride 512B = 32 int4
                sAl[sIdx] = __ldg(gAl + r * 32 + ch);
                sBh[sIdx] = __ldg(gBh + r * 16 + ch);   // B global row stride 256B = 16 int4
                sBl[sIdx] = __ldg(gBl + r * 16 + ch);
            }
        }
        __syncthreads();

#pragma unroll
        for (int ks = 0; ks < 8; ks++) {
            uint32_t ahi[2][4], alo[2][4];
#pragma unroll
            for (int mt = 0; mt < 2; mt++) {
                ldmx4(ahi[mt], aAddr[mt][0] + ks * 32);
                ldmx4(alo[mt], aAddr[mt][1] + ks * 32);
            }
#pragma unroll
            for (int nt = 0; nt < 8; nt++) {
                uint32_t bhi[2], blo[2];
                ldmx2(bhi, bAddrHi + nt * (8 * SROW) + ks * 32);
                ldmx2(blo, bAddrLo + nt * (8 * SROW) + ks * 32);
#pragma unroll
                for (int mt = 0; mt < 2; mt++) {
                    mma16816(acc[mt][nt], ahi[mt], bhi);
                    mma16816(acc[mt][nt], ahi[mt], blo);
                    mma16816(acc[mt][nt], alo[mt], bhi);
                }
            }
        }
    }

    // ---- epilogue: bias + store + BN stats ----
    const int rowbase = tile * 128 + warpRow * 32;
    const int colbase = warpCol * 64;

    float s[8][2], q[8][2];
#pragma unroll
    for (int nt = 0; nt < 8; nt++) { s[nt][0] = s[nt][1] = 0.f; q[nt][0] = q[nt][1] = 0.f; }

#pragma unroll
    for (int mt = 0; mt < 2; mt++) {
        int r0 = rowbase + mt * 16 + (lane >> 2);
        int r1 = r0 + 8;
#pragma unroll
        for (int nt = 0; nt < 8; nt++) {
            int col = colbase + nt * 8 + ((lane & 3) << 1);
            float b0 = BIAS ? __ldg(bias + col) : 0.f;
            float b1 = BIAS ? __ldg(bias + col + 1) : 0.f;
            float v0 = acc[mt][nt][0] + b0;
            float v1 = acc[mt][nt][1] + b1;
            float v2 = acc[mt][nt][2] + b0;
            float v3 = acc[mt][nt][3] + b1;
            if (r0 < N) {
                *(float2*)(H + (size_t)r0 * DIM + col) = make_float2(v0, v1);
                if (STATS) {
                    s[nt][0] += v0; s[nt][1] += v1;
                    q[nt][0] += v0 * v0; q[nt][1] += v1 * v1;
                }
            }
            if (r1 < N) {
                *(float2*)(H + (size_t)r1 * DIM + col) = make_float2(v2, v3);
                if (STATS) {
                    s[nt][0] += v2; s[nt][1] += v3;
                    q[nt][0] += v2 * v2; q[nt][1] += v3 * v3;
                }
            }
        }
    }

    if (STATS) {
#pragma unroll
        for (int nt = 0; nt < 8; nt++) {
#pragma unroll
            for (int p = 0; p < 2; p++) {
                float vs = s[nt][p], vq = q[nt][p];
#pragma unroll
                for (int sh = 4; sh < 32; sh <<= 1) {
                    vs += __shfl_xor_sync(0xFFFFFFFFu, vs, sh);
                    vq += __shfl_xor_sync(0xFFFFFFFFu, vq, sh);
                }
                if (lane < 4) {
                    int col = colbase + nt * 8 + (lane << 1) + p;
                    atomicAdd(&sstats[col], vs);
                    atomicAdd(&sstats[128 + col], vq);
                }
            }
        }
        __syncthreads();
        atomicAdd(&stats[tid], sstats[tid]);
    }
}

// ---------------- BN apply + ReLU + dis-prescale (z = dis * relu(bn(h))) ----------------
// inline BN finalize: first 32 threads compute the 128 scale/shift params into smem
__global__ void bn_apply_kernel(const float* __restrict__ gamma, const float* __restrict__ beta,
                                const float* __restrict__ stats, int N) {
    __shared__ float4 ssc[32], ssh[32];
    int tid = threadIdx.x;
    if (tid < 32) {
        float4 s = ((const float4*)stats)[tid];
        float4 sq = ((const float4*)stats)[32 + tid];
        float4 g = __ldg((const float4*)gamma + tid);
        float4 b = __ldg((const float4*)beta + tid);
        float invn = 1.0f / (float)N;
        float4 mu = make_float4(s.x * invn, s.y * invn, s.z * invn, s.w * invn);
        float4 sc, sh;
        sc.x = g.x * rsqrtf(fmaxf(sq.x * invn - mu.x * mu.x, 0.f) + BN_EPS);
        sc.y = g.y * rsqrtf(fmaxf(sq.y * invn - mu.y * mu.y, 0.f) + BN_EPS);
        sc.z = g.z * rsqrtf(fmaxf(sq.z * invn - mu.z * mu.z, 0.f) + BN_EPS);
        sc.w = g.w * rsqrtf(fmaxf(sq.w * invn - mu.w * mu.w, 0.f) + BN_EPS);
        sh.x = b.x - mu.x * sc.x;
        sh.y = b.y - mu.y * sc.y;
        sh.z = b.z - mu.z * sc.z;
        sh.w = b.w - mu.w * sc.w;
        ssc[tid] = sc; ssh[tid] = sh;
    }
    __syncthreads();
    int i = blockIdx.x * blockDim.x + tid;
    int tot = N * (DIM / 4);
    if (i >= tot) return;
    int n = i >> 5;
    int q = i & 31;
    float4 h = reinterpret_cast<const float4*>(g_h)[i];
    float4 sc = ssc[q];
    float4 sh = ssh[q];
    float d = g_dis[n];
    float4 z;
    z.x = d * fmaxf(fmaf(h.x, sc.x, sh.x), 0.f);
    z.y = d * fmaxf(fmaf(h.y, sc.y, sh.y), 0.f);
    z.z = d * fmaxf(fmaf(h.z, sc.z, sh.z), 0.f);
    z.w = d * fmaxf(fmaf(h.w, sc.w, sh.w), 0.f);
    reinterpret_cast<float4*>(g_z)[i] = z;
}

// ---------------- launch ----------------
extern "C" void kernel_launch(void* const* d_in, const int* in_sizes, int n_in,
                              void* d_out, int out_size) {
    const int*   x_idx  = (const int*)d_in[0];
    const int*   edge   = (const int*)d_in[1];
    const float* emb    = (const float*)d_in[2];
    const float* W_out  = (const float*)d_in[3];
    const float* W_root = (const float*)d_in[4];
    const float* bn0_g  = (const float*)d_in[5];
    const float* bn0_b  = (const float*)d_in[6];
    const float* W_sg1  = (const float*)d_in[7];
    const float* b_sg1  = (const float*)d_in[8];
    const float* bn1_g  = (const float*)d_in[9];
    const float* bn1_b  = (const float*)d_in[10];
    const float* W_sg2  = (const float*)d_in[11];
    const float* b_sg2  = (const float*)d_in[12];
    float* out = (float*)d_out;

    int N = in_sizes[0];
    int E = in_sizes[1] / 2;

    void* hp = nullptr;   cudaGetSymbolAddress(&hp, g_h);
    void* sp = nullptr;   cudaGetSymbolAddress(&sp, g_stats);
    float* Hbuf = (float*)hp;
    float* stats0 = (float*)sp;
    float* stats1 = stats0 + 256;

    cudaFuncSetAttribute(mma_kernel<2, true, false>, cudaFuncAttributeMaxDynamicSharedMemorySize, SMEM_BYTES);
    cudaFuncSetAttribute(mma_kernel<1, true, true>,  cudaFuncAttributeMaxDynamicSharedMemorySize, SMEM_BYTES);
    cudaFuncSetAttribute(mma_kernel<1, false, true>, cudaFuncAttributeMaxDynamicSharedMemorySize, SMEM_BYTES);

    const int nbElem = (N * (DIM / 4) + 255) / 256;
    const int nbNode = (N + 255) / 256;
    const int nbEdgeT = (E + 255) / 256;
    const int nbGath = (N * 32 + 255) / 256;
    const int nbScan = (N + 1023) / 1024;
    const int NT = (N + 127) / 128;

    // CSR build + norms + weight images
    init_zero_kernel<<<nbNode, 256>>>(N);
    deg_bprep_kernel<<<nbEdgeT + 128, 256>>>(edge + E, E, nbEdgeT, W_out, W_root, W_sg1, W_sg2);
    scan1_kernel<<<nbScan, 256>>>(N);
    scan3_kernel<<<nbScan, 256>>>(N, E);
    fill_kernel<<<nbEdgeT, 256>>>(edge, E);

    // layer 0: ClusterGCN -> BN -> ReLU
    gather_kernel<0><<<nbGath, 256>>>(emb, x_idx, N);
    mma_kernel<2, true, false><<<NT, 256, SMEM_BYTES>>>(nullptr, Hbuf, stats0, N, 0);
    bn_apply_kernel<<<nbElem, 256>>>(bn0_g, bn0_b, stats0, N);

    // layer 1: SGConv -> BN -> ReLU
    gather_kernel<1><<<nbGath, 256>>>(emb, x_idx, N);
    mma_kernel<1, true, true><<<NT, 256, SMEM_BYTES>>>(b_sg1, Hbuf, stats1, N, 2);
    bn_apply_kernel<<<nbElem, 256>>>(bn1_g, bn1_b, stats1, N);

    // layer 2: final SGConv -> d_out
    gather_kernel<1><<<nbGath, 256>>>(emb, x_idx, N);
    mma_kernel<1, false, true><<<NT, 256, SMEM_BYTES>>>(b_sg2, out, nullptr, N, 3);
}

// round 13
// speedup vs baseline: 1.8395x; 1.0089x over previous
#include <cuda_runtime.h>
#include <cuda_bf16.h>
#include <cstdint>

#define NMAX 50000
#define NPAD 50048          // 391 tiles * 128 rows
#define EMAX 600000
#define DIM 128
#define BN_EPS 1e-5f

// ---------------- device scratch (no allocations allowed) ----------------
__device__ int   g_cnt[NMAX];
__device__ int   g_start[NMAX + 1];
__device__ int   g_cursor[NMAX];
__device__ int   g_src[EMAX];
__device__ int   g_bsum[64];
__device__ float g_deg_inv[NMAX];
__device__ float g_dis[NMAX];
__device__ __align__(16) float g_h[NMAX * DIM];      // GEMM output (fp32)
__device__ __align__(16) float g_z[NMAX * DIM];      // dis * relu(bn(h)) for next gather
__device__ __align__(16) float g_stats[2][256];      // per-BN-layer col sum / sumsq

// bf16 split images, row-major. A: [NPAD][256 bf16] (=128 u32). Layers 1/2 use cols 0..127.
__device__ __align__(16) uint32_t g_ahi[(size_t)NPAD * 128];
__device__ __align__(16) uint32_t g_alo[(size_t)NPAD * 128];
// B: [sel][128 n][128 k] bf16 = 8192 u32. sel: 0=W_out 1=W_root 2=W_sg1 3=W_sg2
__device__ __align__(16) uint32_t g_bhi[4][8192];
__device__ __align__(16) uint32_t g_blo[4][8192];

// ---------------- helpers ----------------
__device__ __forceinline__ uint32_t smem_u32(const void* p) {
    uint32_t a;
    asm("{ .reg .u64 t; cvta.to.shared.u64 t, %1; cvt.u32.u64 %0, t; }" : "=r"(a) : "l"(p));
    return a;
}
// pack two floats to bf16x2 (low half = first arg)
__device__ __forceinline__ uint32_t bf16pair(float lo, float hi) {
    uint32_t r;
    asm("cvt.rn.bf16x2.f32 %0, %1, %2;" : "=r"(r) : "f"(hi), "f"(lo));
    return r;
}
__device__ __forceinline__ float lo_f(uint32_t p) { return __uint_as_float(p << 16); }
__device__ __forceinline__ float hi_f(uint32_t p) { return __uint_as_float(p & 0xFFFF0000u); }

__device__ __forceinline__ void ldmx4(uint32_t* r, uint32_t addr) {
    asm volatile("ldmatrix.sync.aligned.m8n8.x4.shared.b16 {%0,%1,%2,%3}, [%4];"
                 : "=r"(r[0]), "=r"(r[1]), "=r"(r[2]), "=r"(r[3]) : "r"(addr));
}
__device__ __forceinline__ void ldmx2(uint32_t* r, uint32_t addr) {
    asm volatile("ldmatrix.sync.aligned.m8n8.x2.shared.b16 {%0,%1}, [%2];"
                 : "=r"(r[0]), "=r"(r[1]) : "r"(addr));
}
__device__ __forceinline__ void mma16816(float* d, const uint32_t* a, const uint32_t* b) {
    asm volatile("mma.sync.aligned.m16n8k16.row.col.f32.bf16.bf16.f32 "
                 "{%0,%1,%2,%3}, {%4,%5,%6,%7}, {%8,%9}, {%0,%1,%2,%3};"
                 : "+f"(d[0]), "+f"(d[1]), "+f"(d[2]), "+f"(d[3])
                 : "r"(a[0]), "r"(a[1]), "r"(a[2]), "r"(a[3]), "r"(b[0]), "r"(b[1]));
}

// ---------------- init ----------------
__global__ void init_zero_kernel(int n) {
    int i = blockIdx.x * blockDim.x + threadIdx.x;
    if (i < n) g_cnt[i] = 0;
    if (i < 512) ((float*)g_stats)[i] = 0.f;
}

// ---------------- degree histogram + weight-image prep (merged launch) ----------------
// blocks [0, nbEdge): degree histogram; blocks [nbEdge, nbEdge+128): bprep
__global__ void deg_bprep_kernel(const int* __restrict__ col, int E, int nbEdge,
                                 const float* __restrict__ W_out, const float* __restrict__ W_root,
                                 const float* __restrict__ W_sg1, const float* __restrict__ W_sg2) {
    if (blockIdx.x < (unsigned)nbEdge) {
        int e = blockIdx.x * blockDim.x + threadIdx.x;
        if (e < E) atomicAdd(&g_cnt[col[e]], 1);
    } else {
        int t = (blockIdx.x - nbEdge) * blockDim.x + threadIdx.x;  // 0 .. 32767
        if (t >= 4 * 8192) return;
        int sel = t >> 13;
        int rem = t & 8191;
        int n = rem >> 6;
        int k = (rem & 63) << 1;
        const float* W = (sel == 0) ? W_out : (sel == 1) ? W_root : (sel == 2) ? W_sg1 : W_sg2;
        float x = __ldg(W + n * 128 + k);
        float y = __ldg(W + n * 128 + k + 1);
        uint32_t p = bf16pair(x, y);
        uint32_t q = bf16pair(x - lo_f(p), y - hi_f(p));
        g_bhi[sel][rem] = p;
        g_blo[sel][rem] = q;
    }
}

// ---------------- prefix scan (2 kernels, shuffle-based, minimal barriers) ----------------
__global__ void scan1_kernel(int N) {
    __shared__ int wsum[8];
    int b = blockIdx.x, t = threadIdx.x;
    int lane = t & 31, wid = t >> 5;
    int base = b * 1024 + t * 4;
    int s = 0;
#pragma unroll
    for (int q = 0; q < 4; q++) { int idx = base + q; if (idx < N) s += g_cnt[idx]; }
    int v = s;
#pragma unroll
    for (int d = 16; d > 0; d >>= 1) v += __shfl_down_sync(0xFFFFFFFFu, v, d);
    if (lane == 0) wsum[wid] = v;
    __syncthreads();
    if (t == 0) {
        int tot = 0;
#pragma unroll
        for (int w = 0; w < 8; w++) tot += wsum[w];
        g_bsum[b] = tot;
    }
}
// scan3: shuffle-scan; computes its own block offset from g_bsum (<=64 blocks), writes
// offsets, cursors, and node norms (deg_inv / dis). All accesses coalesced. 2 barriers.
__global__ void scan3_kernel(int N, int E) {
    __shared__ int wtot[8];
    __shared__ int woff[8];
    __shared__ int sboff;
    int b = blockIdx.x, t = threadIdx.x;
    int lane = t & 31, wid = t >> 5;

    // exclusive offset of this block = sum of g_bsum[0..b)  (warp 1 computes it)
    if (wid == 1) {
        int v0 = (lane < b) ? g_bsum[lane] : 0;
        int v1 = (lane + 32 < b) ? g_bsum[lane + 32] : 0;
        int v = v0 + v1;
#pragma unroll
        for (int d = 16; d > 0; d >>= 1) v += __shfl_down_sync(0xFFFFFFFFu, v, d);
        if (lane == 0) sboff = v;
    }

    int base = b * 1024 + t * 4;
    int v[4]; int s = 0;
#pragma unroll
    for (int q = 0; q < 4; q++) { int idx = base + q; v[q] = (idx < N) ? g_cnt[idx] : 0; s += v[q]; }

    // warp inclusive scan of per-thread sums
    int inc = s;
#pragma unroll
    for (int d = 1; d < 32; d <<= 1) {
        int y = __shfl_up_sync(0xFFFFFFFFu, inc, d);
        if (lane >= d) inc += y;
    }
    if (lane == 31) wtot[wid] = inc;
    __syncthreads();

    // warp 0: exclusive scan of the 8 warp totals
    if (wid == 0 && lane < 8) {
        int w = wtot[lane];
#pragma unroll
        for (int d = 1; d < 8; d <<= 1) {
            int y = __shfl_up_sync(0xFFu, w, d);
            if (lane >= d) w += y;
        }
        woff[lane] = w - wtot[lane];   // exclusive
    }
    __syncthreads();

    int run = (inc - s) + woff[wid] + sboff;
#pragma unroll
    for (int q = 0; q < 4; q++) {
        int idx = base + q;
        if (idx < N) {
            g_start[idx] = run;
            g_cursor[idx] = run;
            run += v[q];
            float d = (float)v[q];
            g_deg_inv[idx] = 1.0f / fmaxf(d, 1.0f);
            g_dis[idx] = rsqrtf(d + 1.0f);
        }
    }
    if (b == 0 && t == 0) g_start[N] = E;
}
__global__ void fill_kernel(const int* __restrict__ edge, int E) {
    int e = blockIdx.x * blockDim.x + threadIdx.x;
    if (e < E) {
        int r = __ldg(edge + e);
        int c = __ldg(edge + E + e);
        int pos = atomicAdd(&g_cursor[c], 1);
        g_src[pos] = r;
    }
}

__device__ __forceinline__ void write_split4(uint32_t* hi, uint32_t* lo, int idx2, float4 v) {
    uint32_t p0 = bf16pair(v.x, v.y);
    uint32_t p1 = bf16pair(v.z, v.w);
    uint32_t q0 = bf16pair(v.x - lo_f(p0), v.y - hi_f(p0));
    uint32_t q1 = bf16pair(v.z - lo_f(p1), v.w - hi_f(p1));
    reinterpret_cast<uint2*>(hi)[idx2] = make_uint2(p0, p1);
    reinterpret_cast<uint2*>(lo)[idx2] = make_uint2(q0, q1);
}

// ---------------- gather: one warp per node; writes bf16 split A rows ----------------
// SRC=0 (layer 0): cols 0..127 = deg_inv[n]*sum(emb[x_idx[r]]); cols 128..255 = emb[x_idx[n]]
// SRC=1 (SGConv):  cols 0..127 = dis[n]*(sum(g_z[r]) + g_z[n]),  z already dis-prescaled
template <int SRC>
__global__ void gather_kernel(const float* __restrict__ emb,
                              const int* __restrict__ x_idx, int N) {
    int t = blockIdx.x * blockDim.x + threadIdx.x;
    int n = t >> 5;
    if (n >= N) return;
    int lane = t & 31;
    int s = __ldg(&g_start[n]);
    int e = __ldg(&g_start[n + 1]);
    float4 a0 = make_float4(0.f, 0.f, 0.f, 0.f);
    float4 a1 = make_float4(0.f, 0.f, 0.f, 0.f);
    int i = s;
    for (; i + 2 <= e; i += 2) {
        int r0 = __ldg(&g_src[i]);
        int r1 = __ldg(&g_src[i + 1]);
        const float* p0;
        const float* p1;
        if (SRC == 0) {
            p0 = emb + (size_t)__ldg(x_idx + r0) * DIM;
            p1 = emb + (size_t)__ldg(x_idx + r1) * DIM;
        } else {
            p0 = g_z + (size_t)r0 * DIM;
            p1 = g_z + (size_t)r1 * DIM;
        }
        float4 v0 = __ldg(reinterpret_cast<const float4*>(p0) + lane);
        float4 v1 = __ldg(reinterpret_cast<const float4*>(p1) + lane);
        a0.x += v0.x; a0.y += v0.y; a0.z += v0.z; a0.w += v0.w;
        a1.x += v1.x; a1.y += v1.y; a1.z += v1.z; a1.w += v1.w;
    }
    if (i < e) {
        int r0 = __ldg(&g_src[i]);
        const float* p0 = (SRC == 0) ? emb + (size_t)__ldg(x_idx + r0) * DIM
                                     : g_z + (size_t)r0 * DIM;
        float4 v0 = __ldg(reinterpret_cast<const float4*>(p0) + lane);
        a0.x += v0.x; a0.y += v0.y; a0.z += v0.z; a0.w += v0.w;
    }
    a0.x += a1.x; a0.y += a1.y; a0.z += a1.z; a0.w += a1.w;

    uint32_t* Ah = g_ahi + (size_t)n * 128;
    uint32_t* Al = g_alo + (size_t)n * 128;

    if (SRC == 0) {
        float sc = g_deg_inv[n];
        write_split4(Ah, Al, lane,
                     make_float4(sc * a0.x, sc * a0.y, sc * a0.z, sc * a0.w));
        const float* pr = emb + (size_t)__ldg(x_idx + n) * DIM;
        float4 vr = __ldg(reinterpret_cast<const float4*>(pr) + lane);
        write_split4(Ah, Al, 32 + lane, vr);
    } else {
        float sc = g_dis[n];
        float4 z = __ldg(reinterpret_cast<const float4*>(g_z + (size_t)n * DIM) + lane);
        write_split4(Ah, Al, lane,
                     make_float4(sc * (a0.x + z.x), sc * (a0.y + z.y),
                                 sc * (a0.z + z.z), sc * (a0.w + z.w)));
    }
}

// ---------------- mma.sync GEMM: 128x128 tile per block, bf16 3-term split ----------------
// smem rows padded to 17 x 16B (272B) -> conflict-free ldmatrix
#define SROW 272
#define OFF_AHI 0
#define OFF_ALO 34816
#define OFF_BHI 69632
#define OFF_BLO 104448
#define SMEM_BYTES 139264

template <int KCHUNKS, bool STATS, bool BIAS>
__global__ __launch_bounds__(256, 1)
void mma_kernel(const float* __restrict__ bias, float* __restrict__ H,
                float* __restrict__ stats, int N, int bsel) {
    extern __shared__ __align__(16) char smem[];
    __shared__ float sstats[256];

    const int tid = threadIdx.x;
    const int wid = tid >> 5;
    const int lane = tid & 31;
    const int tile = blockIdx.x;
    const int warpRow = wid & 3;        // 4 row groups of 32
    const int warpCol = wid >> 2;       // 2 col groups of 64

    sstats[tid] = 0.f;

    const uint32_t smemu = smem_u32(smem);

    float acc[2][8][4];
#pragma unroll
    for (int mt = 0; mt < 2; mt++)
#pragma unroll
        for (int nt = 0; nt < 8; nt++)
#pragma unroll
            for (int q = 0; q < 4; q++) acc[mt][nt][q] = 0.f;

    uint32_t aAddr[2][2];   // [mt][hi/lo]
#pragma unroll
    for (int mt = 0; mt < 2; mt++) {
        uint32_t rb = (uint32_t)(warpRow * 32 + mt * 16 + (lane & 15)) * SROW + ((lane >> 4) << 4);
        aAddr[mt][0] = smemu + OFF_AHI + rb;
        aAddr[mt][1] = smemu + OFF_ALO + rb;
    }
    uint32_t bRow = (uint32_t)(warpCol * 64 + (lane & 7)) * SROW + (((lane >> 3) & 1) << 4);
    uint32_t bAddrHi = smemu + OFF_BHI + bRow;
    uint32_t bAddrLo = smemu + OFF_BLO + bRow;

#pragma unroll
    for (int c = 0; c < KCHUNKS; c++) {
        __syncthreads();
        {
            const int4* gAh = (const int4*)(g_ahi + ((size_t)tile * 128) * 128) + c * 16;
            const int4* gAl = (const int4*)(g_alo + ((size_t)tile * 128) * 128) + c * 16;
            const int4* gBh = (const int4*)(g_bhi[bsel + c]);
            const int4* gBl = (const int4*)(g_blo[bsel + c]);
            int4* sAh = (int4*)(smem + OFF_AHI);
            int4* sAl = (int4*)(smem + OFF_ALO);
            int4* sBh = (int4*)(smem + OFF_BHI);
            int4* sBl = (int4*)(smem + OFF_BLO);
#pragma unroll
            for (int it = 0; it < 8; it++) {
                int idx = tid + it * 256;           // 0..2047
                int r = idx >> 4;
                int ch = idx & 15;
                int sIdx = r * 17 + ch;
                sAh[sIdx] = __ldg(gAh + r * 32 + ch);   // A global row stride 512B = 32 int4
                sAl[sIdx] = __ldg(gAl + r * 32 + ch);
                sBh[sIdx] = __ldg(gBh + r * 16 + ch);   // B global row stride 256B = 16 int4
                sBl[sIdx] = __ldg(gBl + r * 16 + ch);
            }
        }
        __syncthreads();

#pragma unroll
        for (int ks = 0; ks < 8; ks++) {
            uint32_t ahi[2][4], alo[2][4];
#pragma unroll
            for (int mt = 0; mt < 2; mt++) {
                ldmx4(ahi[mt], aAddr[mt][0] + ks * 32);
                ldmx4(alo[mt], aAddr[mt][1] + ks * 32);
            }
#pragma unroll
            for (int nt = 0; nt < 8; nt++) {
                uint32_t bhi[2], blo[2];
                ldmx2(bhi, bAddrHi + nt * (8 * SROW) + ks * 32);
                ldmx2(blo, bAddrLo + nt * (8 * SROW) + ks * 32);
#pragma unroll
                for (int mt = 0; mt < 2; mt++) {
                    mma16816(acc[mt][nt], ahi[mt], bhi);
                    mma16816(acc[mt][nt], ahi[mt], blo);
                    mma16816(acc[mt][nt], alo[mt], bhi);
                }
            }
        }
    }

    // ---- epilogue: bias + store + BN stats ----
    const int rowbase = tile * 128 + warpRow * 32;
    const int colbase = warpCol * 64;

    float s[8][2], q[8][2];
#pragma unroll
    for (int nt = 0; nt < 8; nt++) { s[nt][0] = s[nt][1] = 0.f; q[nt][0] = q[nt][1] = 0.f; }

#pragma unroll
    for (int mt = 0; mt < 2; mt++) {
        int r0 = rowbase + mt * 16 + (lane >> 2);
        int r1 = r0 + 8;
#pragma unroll
        for (int nt = 0; nt < 8; nt++) {
            int col = colbase + nt * 8 + ((lane & 3) << 1);
            float b0 = BIAS ? __ldg(bias + col) : 0.f;
            float b1 = BIAS ? __ldg(bias + col + 1) : 0.f;
            float v0 = acc[mt][nt][0] + b0;
            float v1 = acc[mt][nt][1] + b1;
            float v2 = acc[mt][nt][2] + b0;
            float v3 = acc[mt][nt][3] + b1;
            if (r0 < N) {
                *(float2*)(H + (size_t)r0 * DIM + col) = make_float2(v0, v1);
                if (STATS) {
                    s[nt][0] += v0; s[nt][1] += v1;
                    q[nt][0] += v0 * v0; q[nt][1] += v1 * v1;
                }
            }
            if (r1 < N) {
                *(float2*)(H + (size_t)r1 * DIM + col) = make_float2(v2, v3);
                if (STATS) {
                    s[nt][0] += v2; s[nt][1] += v3;
                    q[nt][0] += v2 * v2; q[nt][1] += v3 * v3;
                }
            }
        }
    }

    if (STATS) {
#pragma unroll
        for (int nt = 0; nt < 8; nt++) {
#pragma unroll
            for (int p = 0; p < 2; p++) {
                float vs = s[nt][p], vq = q[nt][p];
#pragma unroll
                for (int sh = 4; sh < 32; sh <<= 1) {
                    vs += __shfl_xor_sync(0xFFFFFFFFu, vs, sh);
                    vq += __shfl_xor_sync(0xFFFFFFFFu, vq, sh);
                }
                if (lane < 4) {
                    int col = colbase + nt * 8 + (lane << 1) + p;
                    atomicAdd(&sstats[col], vs);
                    atomicAdd(&sstats[128 + col], vq);
                }
            }
        }
        __syncthreads();
        atomicAdd(&stats[tid], sstats[tid]);
    }
}

// ---------------- BN apply + ReLU + dis-prescale (z = dis * relu(bn(h))) ----------------
// inline BN finalize: first 32 threads compute the 128 scale/shift params into smem
__global__ void bn_apply_kernel(const float* __restrict__ gamma, const float* __restrict__ beta,
                                const float* __restrict__ stats, int N) {
    __shared__ float4 ssc[32], ssh[32];
    int tid = threadIdx.x;
    if (tid < 32) {
        float4 s = ((const float4*)stats)[tid];
        float4 sq = ((const float4*)stats)[32 + tid];
        float4 g = __ldg((const float4*)gamma + tid);
        float4 b = __ldg((const float4*)beta + tid);
        float invn = 1.0f / (float)N;
        float4 mu = make_float4(s.x * invn, s.y * invn, s.z * invn, s.w * invn);
        float4 sc, sh;
        sc.x = g.x * rsqrtf(fmaxf(sq.x * invn - mu.x * mu.x, 0.f) + BN_EPS);
        sc.y = g.y * rsqrtf(fmaxf(sq.y * invn - mu.y * mu.y, 0.f) + BN_EPS);
        sc.z = g.z * rsqrtf(fmaxf(sq.z * invn - mu.z * mu.z, 0.f) + BN_EPS);
        sc.w = g.w * rsqrtf(fmaxf(sq.w * invn - mu.w * mu.w, 0.f) + BN_EPS);
        sh.x = b.x - mu.x * sc.x;
        sh.y = b.y - mu.y * sc.y;
        sh.z = b.z - mu.z * sc.z;
        sh.w = b.w - mu.w * sc.w;
        ssc[tid] = sc; ssh[tid] = sh;
    }
    __syncthreads();
    int i = blockIdx.x * blockDim.x + tid;
    int tot = N * (DIM / 4);
    if (i >= tot) return;
    int n = i >> 5;
    int q = i & 31;
    float4 h = reinterpret_cast<const float4*>(g_h)[i];
    float4 sc = ssc[q];
    float4 sh = ssh[q];
    float d = g_dis[n];
    float4 z;
    z.x = d * fmaxf(fmaf(h.x, sc.x, sh.x), 0.f);
    z.y = d * fmaxf(fmaf(h.y, sc.y, sh.y), 0.f);
    z.z = d * fmaxf(fmaf(h.z, sc.z, sh.z), 0.f);
    z.w = d * fmaxf(fmaf(h.w, sc.w, sh.w), 0.f);
    reinterpret_cast<float4*>(g_z)[i] = z;
}

// ---------------- launch ----------------
extern "C" void kernel_launch(void* const* d_in, const int* in_sizes, int n_in,
                              void* d_out, int out_size) {
    const int*   x_idx  = (const int*)d_in[0];
    const int*   edge   = (const int*)d_in[1];
    const float* emb    = (const float*)d_in[2];
    const float* W_out  = (const float*)d_in[3];
    const float* W_root = (const float*)d_in[4];
    const float* bn0_g  = (const float*)d_in[5];
    const float* bn0_b  = (const float*)d_in[6];
    const float* W_sg1  = (const float*)d_in[7];
    const float* b_sg1  = (const float*)d_in[8];
    const float* bn1_g  = (const float*)d_in[9];
    const float* bn1_b  = (const float*)d_in[10];
    const float* W_sg2  = (const float*)d_in[11];
    const float* b_sg2  = (const float*)d_in[12];
    float* out = (float*)d_out;

    int N = in_sizes[0];
    int E = in_sizes[1] / 2;

    void* hp = nullptr;   cudaGetSymbolAddress(&hp, g_h);
    void* sp = nullptr;   cudaGetSymbolAddress(&sp, g_stats);
    float* Hbuf = (float*)hp;
    float* stats0 = (float*)sp;
    float* stats1 = stats0 + 256;

    cudaFuncSetAttribute(mma_kernel<2, true, false>, cudaFuncAttributeMaxDynamicSharedMemorySize, SMEM_BYTES);
    cudaFuncSetAttribute(mma_kernel<1, true, true>,  cudaFuncAttributeMaxDynamicSharedMemorySize, SMEM_BYTES);
    cudaFuncSetAttribute(mma_kernel<1, false, true>, cudaFuncAttributeMaxDynamicSharedMemorySize, SMEM_BYTES);

    const int nbElem = (N * (DIM / 4) + 255) / 256;
    const int nbNode = (N + 255) / 256;
    const int nbEdgeT = (E + 255) / 256;
    const int nbGath = (N * 32 + 255) / 256;
    const int nbScan = (N + 1023) / 1024;
    const int NT = (N + 127) / 128;

    // CSR build + norms + weight images
    init_zero_kernel<<<nbNode, 256>>>(N);
    deg_bprep_kernel<<<nbEdgeT + 128, 256>>>(edge + E, E, nbEdgeT, W_out, W_root, W_sg1, W_sg2);
    scan1_kernel<<<nbScan, 256>>>(N);
    scan3_kernel<<<nbScan, 256>>>(N, E);
    fill_kernel<<<nbEdgeT, 256>>>(edge, E);

    // layer 0: ClusterGCN -> BN -> ReLU
    gather_kernel<0><<<nbGath, 256>>>(emb, x_idx, N);
    mma_kernel<2, true, false><<<NT, 256, SMEM_BYTES>>>(nullptr, Hbuf, stats0, N, 0);
    bn_apply_kernel<<<nbElem, 256>>>(bn0_g, bn0_b, stats0, N);

    // layer 1: SGConv -> BN -> ReLU
    gather_kernel<1><<<nbGath, 256>>>(emb, x_idx, N);
    mma_kernel<1, true, true><<<NT, 256, SMEM_BYTES>>>(b_sg1, Hbuf, stats1, N, 2);
    bn_apply_kernel<<<nbElem, 256>>>(bn1_g, bn1_b, stats1, N);

    // layer 2: final SGConv -> d_out
    gather_kernel<1><<<nbGath, 256>>>(emb, x_idx, N);
    mma_kernel<1, false, true><<<NT, 256, SMEM_BYTES>>>(b_sg2, out, nullptr, N, 3);
}